// round 2
// baseline (speedup 1.0000x reference)
#include <cuda_runtime.h>
#include <cuda_bf16.h>
#include <mma.h>

using namespace nvcuda;

// Problem constants
#define BB 8
#define NN 4096
#define DD 768
#define HH 64

// Shared-memory leading dim (floats) for 64-wide tiles: 68 keeps float4 alignment
// (68*4 = 272 B, 16B-aligned) and staggers banks.
#define LD 68

// Device scratch for Q, K, V projections (fp32). 3 x 8 MB.
__device__ float g_q[BB * NN * HH];
__device__ float g_k[BB * NN * HH];
__device__ float g_v[BB * NN * HH];

// ---------------------------------------------------------------------------
// Kernel 1: fused Q/K/V projection.  grid = 512 blocks (64 rows each),
// block = 384 threads (12 warps).  Each warp owns (matrix m, 16-col strip ct)
// and accumulates 4 row-tiles of 16x16 over K = 768 in 64-wide chunks.
// ---------------------------------------------------------------------------
__global__ void proj_kernel(const float* __restrict__ x,
                            const float* __restrict__ Wq, const float* __restrict__ bq,
                            const float* __restrict__ Wk, const float* __restrict__ bk,
                            const float* __restrict__ Wv, const float* __restrict__ bv)
{
    extern __shared__ float sm[];
    float* s_x = sm;             // [64][LD]
    float* s_w = sm + 64 * LD;   // [3][64][LD], reused as output staging

    const int tid  = threadIdx.x;
    const int warp = tid >> 5;
    const int r0   = blockIdx.x * 64;

    const float* Ws[3] = {Wq, Wk, Wv};

    wmma::fragment<wmma::accumulator, 16, 16, 8, float> acc[4];
#pragma unroll
    for (int i = 0; i < 4; i++) wmma::fill_fragment(acc[i], 0.0f);

    const int m  = warp >> 2;   // 0..2 : which projection
    const int ct = warp & 3;    // 0..3 : which 16-col strip

    for (int kc = 0; kc < DD; kc += 64) {
        // load x tile [64 rows][64 cols] as float4
        for (int idx = tid; idx < 64 * 16; idx += 384) {
            int row = idx >> 4, c4 = idx & 15;
            float4 v4 = *(const float4*)(x + (size_t)(r0 + row) * DD + kc + c4 * 4);
            *(float4*)(s_x + row * LD + c4 * 4) = v4;
        }
        // load W chunks: [3][64 k][64 n]
        for (int idx = tid; idx < 3 * 64 * 16; idx += 384) {
            int mm = idx >> 10;
            int rem = idx & 1023;
            int k = rem >> 4, n4 = rem & 15;
            float4 v4 = *(const float4*)(Ws[mm] + (size_t)(kc + k) * HH + n4 * 4);
            *(float4*)(s_w + mm * (64 * LD) + k * LD + n4 * 4) = v4;
        }
        __syncthreads();

#pragma unroll
        for (int ks = 0; ks < 8; ks++) {
            wmma::fragment<wmma::matrix_b, 16, 16, 8, wmma::precision::tf32, wmma::row_major> bf;
            wmma::load_matrix_sync(bf, s_w + m * (64 * LD) + ks * 8 * LD + ct * 16, LD);
#pragma unroll
            for (int i = 0; i < bf.num_elements; i++) bf.x[i] = wmma::__float_to_tf32(bf.x[i]);
#pragma unroll
            for (int rt = 0; rt < 4; rt++) {
                wmma::fragment<wmma::matrix_a, 16, 16, 8, wmma::precision::tf32, wmma::row_major> af;
                wmma::load_matrix_sync(af, s_x + rt * 16 * LD + ks * 8, LD);
#pragma unroll
                for (int i = 0; i < af.num_elements; i++) af.x[i] = wmma::__float_to_tf32(af.x[i]);
                wmma::mma_sync(acc[rt], af, bf, acc[rt]);
            }
        }
        __syncthreads();
    }

    // stage results in s_w, then add bias and write to global scratch
#pragma unroll
    for (int rt = 0; rt < 4; rt++)
        wmma::store_matrix_sync(s_w + m * (64 * LD) + rt * 16 * LD + ct * 16, acc[rt], LD,
                                wmma::mem_row_major);
    __syncthreads();

    const float* bs[3] = {bq, bk, bv};
    float* outs[3] = {g_q, g_k, g_v};
    for (int mm = 0; mm < 3; mm++) {
        for (int idx = tid; idx < 64 * 64; idx += 384) {
            int row = idx >> 6, col = idx & 63;
            outs[mm][(size_t)(r0 + row) * HH + col] =
                s_w[mm * (64 * LD) + row * LD + col] + bs[mm][col];
        }
    }
}

// ---------------------------------------------------------------------------
// Kernel 2: flash attention.  grid = (64 q-tiles, 8 batches), 256 threads.
// 64-row Q tile in smem; loop over 64 key-blocks of 64; online softmax with
// per-row (m, l) state; O accumulated in smem via wmma.
// ---------------------------------------------------------------------------
__global__ void attn_kernel(float* __restrict__ out)
{
    extern __shared__ float sm[];
    float* s_q  = sm;                 // [64][LD]
    float* s_k  = s_q  + 64 * LD;     // [64][LD]
    float* s_v  = s_k  + 64 * LD;     // [64][LD]
    float* s_sp = s_v  + 64 * LD;     // [64][LD]  S, overwritten in place by P
    float* s_o  = s_sp + 64 * LD;     // [64][LD]
    float* s_m  = s_o  + 64 * LD;     // [64]
    float* s_l  = s_m  + 64;          // [64]

    const int tid  = threadIdx.x;
    const int warp = tid >> 5;
    const int lane = tid & 31;
    const int b    = blockIdx.y;
    const int q0   = blockIdx.x * 64;
    const float scale = 0.125f;       // 1/sqrt(64)

    // load Q tile, zero O, init m/l
    for (int idx = tid; idx < 64 * 16; idx += 256) {
        int row = idx >> 4, c4 = idx & 15;
        *(float4*)(s_q + row * LD + c4 * 4) =
            *(const float4*)(g_q + (size_t)(b * NN + q0 + row) * HH + c4 * 4);
        float4 z = {0.f, 0.f, 0.f, 0.f};
        *(float4*)(s_o + row * LD + c4 * 4) = z;
    }
    if (tid < 64) { s_m[tid] = -1e30f; s_l[tid] = 0.f; }
    __syncthreads();

    const int rt  = warp >> 1;        // 0..3 : row tile
    const int ct0 = (warp & 1) * 2;   // 0 or 2 : first of two col tiles

    for (int kb = 0; kb < NN / 64; kb++) {
        const int k0 = kb * 64;
        // load K, V tiles
        for (int idx = tid; idx < 64 * 16; idx += 256) {
            int row = idx >> 4, c4 = idx & 15;
            *(float4*)(s_k + row * LD + c4 * 4) =
                *(const float4*)(g_k + (size_t)(b * NN + k0 + row) * HH + c4 * 4);
            *(float4*)(s_v + row * LD + c4 * 4) =
                *(const float4*)(g_v + (size_t)(b * NN + k0 + row) * HH + c4 * 4);
        }
        __syncthreads();

        // S = Q @ K^T  (each warp: 2 tiles of 16x16)
        {
            wmma::fragment<wmma::accumulator, 16, 16, 8, float> sacc[2];
            wmma::fill_fragment(sacc[0], 0.0f);
            wmma::fill_fragment(sacc[1], 0.0f);
#pragma unroll
            for (int ks = 0; ks < 8; ks++) {
                wmma::fragment<wmma::matrix_a, 16, 16, 8, wmma::precision::tf32, wmma::row_major> af;
                wmma::load_matrix_sync(af, s_q + rt * 16 * LD + ks * 8, LD);
#pragma unroll
                for (int i = 0; i < af.num_elements; i++) af.x[i] = wmma::__float_to_tf32(af.x[i]);
#pragma unroll
                for (int j = 0; j < 2; j++) {
                    // col_major view of K rows => K^T
                    wmma::fragment<wmma::matrix_b, 16, 16, 8, wmma::precision::tf32, wmma::col_major> bf;
                    wmma::load_matrix_sync(bf, s_k + (ct0 + j) * 16 * LD + ks * 8, LD);
#pragma unroll
                    for (int i = 0; i < bf.num_elements; i++) bf.x[i] = wmma::__float_to_tf32(bf.x[i]);
                    wmma::mma_sync(sacc[j], af, bf, sacc[j]);
                }
            }
#pragma unroll
            for (int j = 0; j < 2; j++)
                wmma::store_matrix_sync(s_sp + rt * 16 * LD + (ct0 + j) * 16, sacc[j], LD,
                                        wmma::mem_row_major);
        }
        __syncthreads();

        // online softmax: warp w owns rows 8w..8w+7
#pragma unroll
        for (int rr = 0; rr < 8; rr++) {
            int r = warp * 8 + rr;
            float v0 = s_sp[r * LD + lane] * scale;
            float v1 = s_sp[r * LD + 32 + lane] * scale;
            float mx = fmaxf(v0, v1);
#pragma unroll
            for (int off = 16; off; off >>= 1)
                mx = fmaxf(mx, __shfl_xor_sync(0xffffffffu, mx, off));
            float m_old = s_m[r];
            float m_new = fmaxf(m_old, mx);
            float p0 = __expf(v0 - m_new);
            float p1 = __expf(v1 - m_new);
            float s = p0 + p1;
#pragma unroll
            for (int off = 16; off; off >>= 1)
                s += __shfl_xor_sync(0xffffffffu, s, off);
            // P in place of S
            s_sp[r * LD + lane]      = p0;
            s_sp[r * LD + 32 + lane] = p1;
            if (kb == 0) {
                if (lane == 0) { s_m[r] = m_new; s_l[r] = s; }
            } else {
                float alpha = __expf(m_old - m_new);
                if (lane == 0) { s_m[r] = m_new; s_l[r] = s_l[r] * alpha + s; }
                // rescale O row
                s_o[r * LD + lane]      *= alpha;
                s_o[r * LD + 32 + lane] *= alpha;
            }
        }
        __syncthreads();

        // O += P @ V
        {
            wmma::fragment<wmma::accumulator, 16, 16, 8, float> oacc[2];
#pragma unroll
            for (int j = 0; j < 2; j++)
                wmma::load_matrix_sync(oacc[j], s_o + rt * 16 * LD + (ct0 + j) * 16, LD,
                                       wmma::mem_row_major);
#pragma unroll
            for (int ks = 0; ks < 8; ks++) {
                wmma::fragment<wmma::matrix_a, 16, 16, 8, wmma::precision::tf32, wmma::row_major> af;
                wmma::load_matrix_sync(af, s_sp + rt * 16 * LD + ks * 8, LD);
#pragma unroll
                for (int i = 0; i < af.num_elements; i++) af.x[i] = wmma::__float_to_tf32(af.x[i]);
#pragma unroll
                for (int j = 0; j < 2; j++) {
                    wmma::fragment<wmma::matrix_b, 16, 16, 8, wmma::precision::tf32, wmma::row_major> bf;
                    wmma::load_matrix_sync(bf, s_v + ks * 8 * LD + (ct0 + j) * 16, LD);
#pragma unroll
                    for (int i = 0; i < bf.num_elements; i++) bf.x[i] = wmma::__float_to_tf32(bf.x[i]);
                    wmma::mma_sync(oacc[j], af, bf, oacc[j]);
                }
            }
#pragma unroll
            for (int j = 0; j < 2; j++)
                wmma::store_matrix_sync(s_o + rt * 16 * LD + (ct0 + j) * 16, oacc[j], LD,
                                        wmma::mem_row_major);
        }
        __syncthreads();
    }

    // final normalize + write
    for (int idx = tid; idx < 64 * 64; idx += 256) {
        int row = idx >> 6, col = idx & 63;
        out[(size_t)(b * NN + q0 + row) * HH + col] = s_o[row * LD + col] / s_l[row];
    }
}

// ---------------------------------------------------------------------------
extern "C" void kernel_launch(void* const* d_in, const int* in_sizes, int n_in,
                              void* d_out, int out_size)
{
    const float* x  = (const float*)d_in[0];
    const float* Wq = (const float*)d_in[1];
    const float* bq = (const float*)d_in[2];
    const float* Wk = (const float*)d_in[3];
    const float* bk = (const float*)d_in[4];
    const float* Wv = (const float*)d_in[5];
    const float* bv = (const float*)d_in[6];
    float* out = (float*)d_out;

    const int smem_proj = (64 * LD + 3 * 64 * LD) * (int)sizeof(float);       // 69632
    const int smem_attn = (5 * 64 * LD + 128) * (int)sizeof(float);           // 87552

    (void)cudaFuncSetAttribute(proj_kernel, cudaFuncAttributeMaxDynamicSharedMemorySize, smem_proj);
    (void)cudaFuncSetAttribute(attn_kernel, cudaFuncAttributeMaxDynamicSharedMemorySize, smem_attn);

    proj_kernel<<<(BB * NN) / 64, 384, smem_proj>>>(x, Wq, bq, Wk, bk, Wv, bv);
    attn_kernel<<<dim3(NN / 64, BB), 256, smem_attn>>>(out);
}

// round 4
// speedup vs baseline: 1.1937x; 1.1937x over previous
#include <cuda_runtime.h>
#include <cuda_bf16.h>
#include <cstdint>
#include <mma.h>

using namespace nvcuda;

// Problem constants
#define BB 8
#define NN 4096
#define DD 768
#define HH 64

// Shared-memory leading dim (floats): 68 keeps float4 alignment and staggers banks.
#define LD 68

// Device scratch for Q, K, V projections (fp32). 3 x 8 MB.
__device__ float g_q[BB * NN * HH];
__device__ float g_k[BB * NN * HH];
__device__ float g_v[BB * NN * HH];

// ---------------------------------------------------------------------------
// cp.async helpers
// ---------------------------------------------------------------------------
__device__ __forceinline__ void cp_async16(float* smem_dst, const float* gmem_src) {
    unsigned s = (unsigned)__cvta_generic_to_shared(smem_dst);
    asm volatile("cp.async.cg.shared.global [%0], [%1], 16;\n" :: "r"(s), "l"(gmem_src));
}
__device__ __forceinline__ void cp_async_commit() {
    asm volatile("cp.async.commit_group;\n");
}

// ---------------------------------------------------------------------------
// Kernel 1: fused Q/K/V projection (unchanged from R2 — known correct).
// grid = 512 blocks (64 rows each), block = 384 threads (12 warps).
// ---------------------------------------------------------------------------
__global__ void proj_kernel(const float* __restrict__ x,
                            const float* __restrict__ Wq, const float* __restrict__ bq,
                            const float* __restrict__ Wk, const float* __restrict__ bk,
                            const float* __restrict__ Wv, const float* __restrict__ bv)
{
    extern __shared__ float sm[];
    float* s_x = sm;             // [64][LD]
    float* s_w = sm + 64 * LD;   // [3][64][LD], reused as output staging

    const int tid  = threadIdx.x;
    const int warp = tid >> 5;
    const int r0   = blockIdx.x * 64;

    const float* Ws[3] = {Wq, Wk, Wv};

    wmma::fragment<wmma::accumulator, 16, 16, 8, float> acc[4];
#pragma unroll
    for (int i = 0; i < 4; i++) wmma::fill_fragment(acc[i], 0.0f);

    const int m  = warp >> 2;   // 0..2 : which projection
    const int ct = warp & 3;    // 0..3 : which 16-col strip

    for (int kc = 0; kc < DD; kc += 64) {
        for (int idx = tid; idx < 64 * 16; idx += 384) {
            int row = idx >> 4, c4 = idx & 15;
            float4 v4 = *(const float4*)(x + (size_t)(r0 + row) * DD + kc + c4 * 4);
            *(float4*)(s_x + row * LD + c4 * 4) = v4;
        }
        for (int idx = tid; idx < 3 * 64 * 16; idx += 384) {
            int mm = idx >> 10;
            int rem = idx & 1023;
            int k = rem >> 4, n4 = rem & 15;
            float4 v4 = *(const float4*)(Ws[mm] + (size_t)(kc + k) * HH + n4 * 4);
            *(float4*)(s_w + mm * (64 * LD) + k * LD + n4 * 4) = v4;
        }
        __syncthreads();

#pragma unroll
        for (int ks = 0; ks < 8; ks++) {
            wmma::fragment<wmma::matrix_b, 16, 16, 8, wmma::precision::tf32, wmma::row_major> bf;
            wmma::load_matrix_sync(bf, s_w + m * (64 * LD) + ks * 8 * LD + ct * 16, LD);
#pragma unroll
            for (int i = 0; i < bf.num_elements; i++) bf.x[i] = wmma::__float_to_tf32(bf.x[i]);
#pragma unroll
            for (int rt = 0; rt < 4; rt++) {
                wmma::fragment<wmma::matrix_a, 16, 16, 8, wmma::precision::tf32, wmma::row_major> af;
                wmma::load_matrix_sync(af, s_x + rt * 16 * LD + ks * 8, LD);
#pragma unroll
                for (int i = 0; i < af.num_elements; i++) af.x[i] = wmma::__float_to_tf32(af.x[i]);
                wmma::mma_sync(acc[rt], af, bf, acc[rt]);
            }
        }
        __syncthreads();
    }

#pragma unroll
    for (int rt = 0; rt < 4; rt++)
        wmma::store_matrix_sync(s_w + m * (64 * LD) + rt * 16 * LD + ct * 16, acc[rt], LD,
                                wmma::mem_row_major);
    __syncthreads();

    const float* bs[3] = {bq, bk, bv};
    float* outs[3] = {g_q, g_k, g_v};
    for (int mm = 0; mm < 3; mm++) {
        for (int idx = tid; idx < 64 * 64; idx += 384) {
            int row = idx >> 6, col = idx & 63;
            outs[mm][(size_t)(r0 + row) * HH + col] =
                s_w[mm * (64 * LD) + row * LD + col] + bs[mm][col];
        }
    }
}

// ---------------------------------------------------------------------------
// Kernel 2: flash attention, no-max softmax, register-resident O.
// grid = (64 q-tiles, 8 batches), 256 threads (8 warps).
// Per warp: rt = warp>>1 row tile (16 rows), ct0 = (warp&1)*2 col-tile pair.
// O and l accumulate in register fragments for the whole key loop.
// K/V double-buffered via cp.async.
// ---------------------------------------------------------------------------
__global__ void __launch_bounds__(256, 2) attn_kernel(float* __restrict__ out)
{
    extern __shared__ float sm[];
    float* s_k    = sm;                    // [2][64][LD]
    float* s_v    = s_k + 2 * 64 * LD;     // [2][64][LD]
    float* s_sp   = s_v + 2 * 64 * LD;     // [64][LD]  Q staging, then P, then O staging
    float* s_ones = s_sp + 64 * LD;        // [8][16]   ones B-tile (col 0 = 1)

    const int tid  = threadIdx.x;
    const int warp = tid >> 5;
    const int lane = tid & 31;
    const int b    = blockIdx.y;
    const int q0   = blockIdx.x * 64;
    const float scale = 0.125f;            // 1/sqrt(64)

    const int rt  = warp >> 1;             // 0..3
    const int ct0 = (warp & 1) * 2;        // 0 or 2

    // ---- stage Q (pre-scaled) into s_sp, build ones tile ----
    for (int idx = tid; idx < 64 * 16; idx += 256) {
        int row = idx >> 4, c4 = idx & 15;
        float4 v4 = *(const float4*)(g_q + (size_t)(b * NN + q0 + row) * HH + c4 * 4);
        v4.x *= scale; v4.y *= scale; v4.z *= scale; v4.w *= scale;
        *(float4*)(s_sp + row * LD + c4 * 4) = v4;
    }
    if (tid < 128) s_ones[tid] = ((tid & 15) == 0) ? 1.0f : 0.0f;
    __syncthreads();

    // ---- persistent register fragments ----
    wmma::fragment<wmma::matrix_a, 16, 16, 8, wmma::precision::tf32, wmma::row_major> qf[8];
#pragma unroll
    for (int ks = 0; ks < 8; ks++) {
        wmma::load_matrix_sync(qf[ks], s_sp + rt * 16 * LD + ks * 8, LD);
#pragma unroll
        for (int i = 0; i < qf[ks].num_elements; i++)
            qf[ks].x[i] = wmma::__float_to_tf32(qf[ks].x[i]);
    }
    wmma::fragment<wmma::matrix_b, 16, 16, 8, wmma::precision::tf32, wmma::row_major> onesf;
    wmma::load_matrix_sync(onesf, s_ones, 16);
#pragma unroll
    for (int i = 0; i < onesf.num_elements; i++)
        onesf.x[i] = wmma::__float_to_tf32(onesf.x[i]);

    wmma::fragment<wmma::accumulator, 16, 16, 8, float> oacc[2], lacc;
    wmma::fill_fragment(oacc[0], 0.0f);
    wmma::fill_fragment(oacc[1], 0.0f);
    wmma::fill_fragment(lacc, 0.0f);
    __syncthreads();   // qf loads done before s_sp is reused for P

    // ---- prologue: async-load K/V block 0 into buffer 0 ----
    const float* gk = g_k + (size_t)b * NN * HH;
    const float* gv = g_v + (size_t)b * NN * HH;
    {
        const int row = tid >> 2;           // 4 float4 per thread per tile
        const int c4a = (tid & 3) * 4;
#pragma unroll
        for (int u = 0; u < 4; u++) {
            cp_async16(s_k + row * LD + (c4a + u) * 4, gk + (size_t)row * HH + (c4a + u) * 4);
            cp_async16(s_v + row * LD + (c4a + u) * 4, gv + (size_t)row * HH + (c4a + u) * 4);
        }
        cp_async_commit();
    }

    for (int kb = 0; kb < NN / 64; kb++) {
        const int cur = kb & 1;
        const int nxt = cur ^ 1;

        if (kb < NN / 64 - 1) {
            const int k0n = (kb + 1) * 64;
            const int row = tid >> 2;
            const int c4a = (tid & 3) * 4;
#pragma unroll
            for (int u = 0; u < 4; u++) {
                cp_async16(s_k + nxt * 64 * LD + row * LD + (c4a + u) * 4,
                           gk + (size_t)(k0n + row) * HH + (c4a + u) * 4);
                cp_async16(s_v + nxt * 64 * LD + row * LD + (c4a + u) * 4,
                           gv + (size_t)(k0n + row) * HH + (c4a + u) * 4);
            }
            cp_async_commit();
            asm volatile("cp.async.wait_group 1;\n");
        } else {
            asm volatile("cp.async.wait_group 0;\n");
        }
        __syncthreads();

        // ---- S = Q @ K^T, then P = exp(S) elementwise on the accumulator ----
        float* kbuf = s_k + cur * 64 * LD;
        wmma::fragment<wmma::accumulator, 16, 16, 8, float> sacc[2];
        wmma::fill_fragment(sacc[0], 0.0f);
        wmma::fill_fragment(sacc[1], 0.0f);
#pragma unroll
        for (int ks = 0; ks < 8; ks++) {
#pragma unroll
            for (int j = 0; j < 2; j++) {
                wmma::fragment<wmma::matrix_b, 16, 16, 8, wmma::precision::tf32, wmma::col_major> bf;
                wmma::load_matrix_sync(bf, kbuf + (ct0 + j) * 16 * LD + ks * 8, LD);
#pragma unroll
                for (int i = 0; i < bf.num_elements; i++) bf.x[i] = wmma::__float_to_tf32(bf.x[i]);
                wmma::mma_sync(sacc[j], qf[ks], bf, sacc[j]);
            }
        }
#pragma unroll
        for (int j = 0; j < 2; j++) {
#pragma unroll
            for (int i = 0; i < sacc[j].num_elements; i++)
                sacc[j].x[i] = __expf(sacc[j].x[i]);
            wmma::store_matrix_sync(s_sp + rt * 16 * LD + (ct0 + j) * 16, sacc[j], LD,
                                    wmma::mem_row_major);
        }
        __syncthreads();

        // ---- O += P @ V ;  l += P @ ones ----
        float* vbuf = s_v + cur * 64 * LD;
#pragma unroll
        for (int ks = 0; ks < 8; ks++) {
            wmma::fragment<wmma::matrix_a, 16, 16, 8, wmma::precision::tf32, wmma::row_major> af;
            wmma::load_matrix_sync(af, s_sp + rt * 16 * LD + ks * 8, LD);
#pragma unroll
            for (int i = 0; i < af.num_elements; i++) af.x[i] = wmma::__float_to_tf32(af.x[i]);
#pragma unroll
            for (int j = 0; j < 2; j++) {
                wmma::fragment<wmma::matrix_b, 16, 16, 8, wmma::precision::tf32, wmma::row_major> bf;
                wmma::load_matrix_sync(bf, vbuf + ks * 8 * LD + (ct0 + j) * 16, LD);
#pragma unroll
                for (int i = 0; i < bf.num_elements; i++) bf.x[i] = wmma::__float_to_tf32(bf.x[i]);
                wmma::mma_sync(oacc[j], af, bf, oacc[j]);
            }
            if (ct0 == 0) wmma::mma_sync(lacc, af, onesf, lacc);
        }
        __syncthreads();   // protect s_sp (next P) and s_v[cur] (overwritten at kb+2)
    }

    // ---- epilogue: O to s_sp, l (col 0) to s_k rows ----
#pragma unroll
    for (int j = 0; j < 2; j++)
        wmma::store_matrix_sync(s_sp + rt * 16 * LD + (ct0 + j) * 16, oacc[j], LD,
                                wmma::mem_row_major);
    if (ct0 == 0)
        wmma::store_matrix_sync(s_k + rt * 16 * LD, lacc, LD, wmma::mem_row_major);
    __syncthreads();

    for (int idx = tid; idx < 64 * 64; idx += 256) {
        int row = idx >> 6, col = idx & 63;
        out[(size_t)(b * NN + q0 + row) * HH + col] =
            s_sp[row * LD + col] / s_k[row * LD];
    }
}

// ---------------------------------------------------------------------------
extern "C" void kernel_launch(void* const* d_in, const int* in_sizes, int n_in,
                              void* d_out, int out_size)
{
    const float* x  = (const float*)d_in[0];
    const float* Wq = (const float*)d_in[1];
    const float* bq = (const float*)d_in[2];
    const float* Wk = (const float*)d_in[3];
    const float* bk = (const float*)d_in[4];
    const float* Wv = (const float*)d_in[5];
    const float* bv = (const float*)d_in[6];
    float* out = (float*)d_out;

    const int smem_proj = (64 * LD + 3 * 64 * LD) * (int)sizeof(float);          // 69632
    const int smem_attn = (5 * 64 * LD + 128 + 32) * (int)sizeof(float);         // ~87.7KB

    (void)cudaFuncSetAttribute(proj_kernel, cudaFuncAttributeMaxDynamicSharedMemorySize, smem_proj);
    (void)cudaFuncSetAttribute(attn_kernel, cudaFuncAttributeMaxDynamicSharedMemorySize, smem_attn);

    proj_kernel<<<(BB * NN) / 64, 384, smem_proj>>>(x, Wq, bq, Wk, bk, Wv, bv);
    attn_kernel<<<dim3(NN / 64, BB), 256, smem_attn>>>(out);
}

// round 5
// speedup vs baseline: 1.2343x; 1.0340x over previous
#include <cuda_runtime.h>
#include <cuda_bf16.h>
#include <cstdint>
#include <mma.h>

using namespace nvcuda;

// Problem constants
#define BB 8
#define NN 4096
#define DD 768
#define HH 64

// Shared-memory leading dim (floats): 68 keeps float4 alignment and staggers banks.
#define LD 68

// Device scratch for Q, K, V projections (fp32 values pre-rounded to tf32).
__device__ float g_q[BB * NN * HH];
__device__ float g_k[BB * NN * HH];
__device__ float g_v[BB * NN * HH];

// ---------------------------------------------------------------------------
// cp.async helpers
// ---------------------------------------------------------------------------
__device__ __forceinline__ void cp_async16(float* smem_dst, const float* gmem_src) {
    unsigned s = (unsigned)__cvta_generic_to_shared(smem_dst);
    asm volatile("cp.async.cg.shared.global [%0], [%1], 16;\n" :: "r"(s), "l"(gmem_src));
}
__device__ __forceinline__ void cp_async_commit() {
    asm volatile("cp.async.commit_group;\n");
}
__device__ __forceinline__ void pair_bar(int id) {
    asm volatile("bar.sync %0, 64;\n" :: "r"(id) : "memory");
}

// ---------------------------------------------------------------------------
// Kernel 1: fused Q/K/V projection. Epilogue now pre-rounds outputs to tf32
// so attn_kernel can skip all per-fragment __float_to_tf32 loops.
// ---------------------------------------------------------------------------
__global__ void proj_kernel(const float* __restrict__ x,
                            const float* __restrict__ Wq, const float* __restrict__ bq,
                            const float* __restrict__ Wk, const float* __restrict__ bk,
                            const float* __restrict__ Wv, const float* __restrict__ bv)
{
    extern __shared__ float sm[];
    float* s_x = sm;             // [64][LD]
    float* s_w = sm + 64 * LD;   // [3][64][LD], reused as output staging

    const int tid  = threadIdx.x;
    const int warp = tid >> 5;
    const int r0   = blockIdx.x * 64;

    const float* Ws[3] = {Wq, Wk, Wv};

    wmma::fragment<wmma::accumulator, 16, 16, 8, float> acc[4];
#pragma unroll
    for (int i = 0; i < 4; i++) wmma::fill_fragment(acc[i], 0.0f);

    const int m  = warp >> 2;   // 0..2 : which projection
    const int ct = warp & 3;    // 0..3 : which 16-col strip

    for (int kc = 0; kc < DD; kc += 64) {
        for (int idx = tid; idx < 64 * 16; idx += 384) {
            int row = idx >> 4, c4 = idx & 15;
            float4 v4 = *(const float4*)(x + (size_t)(r0 + row) * DD + kc + c4 * 4);
            *(float4*)(s_x + row * LD + c4 * 4) = v4;
        }
        for (int idx = tid; idx < 3 * 64 * 16; idx += 384) {
            int mm = idx >> 10;
            int rem = idx & 1023;
            int k = rem >> 4, n4 = rem & 15;
            float4 v4 = *(const float4*)(Ws[mm] + (size_t)(kc + k) * HH + n4 * 4);
            *(float4*)(s_w + mm * (64 * LD) + k * LD + n4 * 4) = v4;
        }
        __syncthreads();

#pragma unroll
        for (int ks = 0; ks < 8; ks++) {
            wmma::fragment<wmma::matrix_b, 16, 16, 8, wmma::precision::tf32, wmma::row_major> bf;
            wmma::load_matrix_sync(bf, s_w + m * (64 * LD) + ks * 8 * LD + ct * 16, LD);
#pragma unroll
            for (int i = 0; i < bf.num_elements; i++) bf.x[i] = wmma::__float_to_tf32(bf.x[i]);
#pragma unroll
            for (int rt = 0; rt < 4; rt++) {
                wmma::fragment<wmma::matrix_a, 16, 16, 8, wmma::precision::tf32, wmma::row_major> af;
                wmma::load_matrix_sync(af, s_x + rt * 16 * LD + ks * 8, LD);
#pragma unroll
                for (int i = 0; i < af.num_elements; i++) af.x[i] = wmma::__float_to_tf32(af.x[i]);
                wmma::mma_sync(acc[rt], af, bf, acc[rt]);
            }
        }
        __syncthreads();
    }

#pragma unroll
    for (int rt = 0; rt < 4; rt++)
        wmma::store_matrix_sync(s_w + m * (64 * LD) + rt * 16 * LD + ct * 16, acc[rt], LD,
                                wmma::mem_row_major);
    __syncthreads();

    const float* bs[3] = {bq, bk, bv};
    float* outs[3] = {g_q, g_k, g_v};
    for (int mm = 0; mm < 3; mm++) {
        for (int idx = tid; idx < 64 * 64; idx += 384) {
            int row = idx >> 6, col = idx & 63;
            // pre-round to tf32: attn consumes these directly without cvt
            outs[mm][(size_t)(r0 + row) * HH + col] =
                wmma::__float_to_tf32(s_w[mm * (64 * LD) + row * LD + col] + bs[mm][col]);
        }
    }
}

// ---------------------------------------------------------------------------
// Kernel 2: flash attention, no-max softmax, register-resident O/l.
// 1 block sync + 1 pair barrier per key block. All operands pre-tf32.
// ---------------------------------------------------------------------------
__global__ void __launch_bounds__(256, 2) attn_kernel(float* __restrict__ out)
{
    extern __shared__ float sm[];
    float* s_k    = sm;                    // [2][64][LD]
    float* s_v    = s_k + 2 * 64 * LD;     // [2][64][LD]
    float* s_sp   = s_v + 2 * 64 * LD;     // [64][LD]  Q staging, then P, then O staging
    float* s_ones = s_sp + 64 * LD;        // [8][16]   ones B-tile (col 0 = 1)

    const int tid  = threadIdx.x;
    const int warp = tid >> 5;
    const int b    = blockIdx.y;
    const int q0   = blockIdx.x * 64;
    const float scale = 0.125f;            // 1/sqrt(64), exact power of two

    const int rt  = warp >> 1;             // 0..3
    const int ct0 = (warp & 1) * 2;        // 0 or 2

    // ---- stage Q (pre-scaled; scale preserves tf32) into s_sp, ones tile ----
    for (int idx = tid; idx < 64 * 16; idx += 256) {
        int row = idx >> 4, c4 = idx & 15;
        float4 v4 = *(const float4*)(g_q + (size_t)(b * NN + q0 + row) * HH + c4 * 4);
        v4.x *= scale; v4.y *= scale; v4.z *= scale; v4.w *= scale;
        *(float4*)(s_sp + row * LD + c4 * 4) = v4;
    }
    if (tid < 128) s_ones[tid] = ((tid & 15) == 0) ? 1.0f : 0.0f;
    __syncthreads();

    // ---- persistent register fragments (already tf32, no cvt) ----
    wmma::fragment<wmma::matrix_a, 16, 16, 8, wmma::precision::tf32, wmma::row_major> qf[8];
#pragma unroll
    for (int ks = 0; ks < 8; ks++)
        wmma::load_matrix_sync(qf[ks], s_sp + rt * 16 * LD + ks * 8, LD);

    wmma::fragment<wmma::matrix_b, 16, 16, 8, wmma::precision::tf32, wmma::row_major> onesf;
    wmma::load_matrix_sync(onesf, s_ones, 16);

    wmma::fragment<wmma::accumulator, 16, 16, 8, float> oacc[2], lacc;
    wmma::fill_fragment(oacc[0], 0.0f);
    wmma::fill_fragment(oacc[1], 0.0f);
    wmma::fill_fragment(lacc, 0.0f);

    // ---- prologue: async-load K/V block 0 into buffer 0 ----
    const float* gk = g_k + (size_t)b * NN * HH;
    const float* gv = g_v + (size_t)b * NN * HH;
    const int lrow = tid >> 2;             // 4 float4 per thread per tile
    const int lc4  = (tid & 3) * 4;
#pragma unroll
    for (int u = 0; u < 4; u++) {
        cp_async16(s_k + lrow * LD + (lc4 + u) * 4, gk + (size_t)lrow * HH + (lc4 + u) * 4);
        cp_async16(s_v + lrow * LD + (lc4 + u) * 4, gv + (size_t)lrow * HH + (lc4 + u) * 4);
    }
    cp_async_commit();

    for (int kb = 0; kb < NN / 64; kb++) {
        const int cur = kb & 1;
        const int nxt = cur ^ 1;

        // wait for current K/V, then single block-wide barrier:
        // (a) cur buffer visible to all, (b) all warps done with prev iteration
        asm volatile("cp.async.wait_group 0;\n");
        __syncthreads();

        // prefetch next block (issued AFTER the barrier -> no WAR race on nxt)
        if (kb < NN / 64 - 1) {
            const int k0n = (kb + 1) * 64;
#pragma unroll
            for (int u = 0; u < 4; u++) {
                cp_async16(s_k + nxt * 64 * LD + lrow * LD + (lc4 + u) * 4,
                           gk + (size_t)(k0n + lrow) * HH + (lc4 + u) * 4);
                cp_async16(s_v + nxt * 64 * LD + lrow * LD + (lc4 + u) * 4,
                           gv + (size_t)(k0n + lrow) * HH + (lc4 + u) * 4);
            }
            cp_async_commit();
        }

        // ---- S = Q @ K^T ----
        float* kbuf = s_k + cur * 64 * LD;
        wmma::fragment<wmma::accumulator, 16, 16, 8, float> sacc[2];
        wmma::fill_fragment(sacc[0], 0.0f);
        wmma::fill_fragment(sacc[1], 0.0f);
#pragma unroll
        for (int ks = 0; ks < 8; ks++) {
#pragma unroll
            for (int j = 0; j < 2; j++) {
                wmma::fragment<wmma::matrix_b, 16, 16, 8, wmma::precision::tf32, wmma::col_major> bf;
                wmma::load_matrix_sync(bf, kbuf + (ct0 + j) * 16 * LD + ks * 8, LD);
                wmma::mma_sync(sacc[j], qf[ks], bf, sacc[j]);
            }
        }

        // ---- P = exp(S), rounded to tf32 so the reload needs no cvt ----
#pragma unroll
        for (int j = 0; j < 2; j++) {
#pragma unroll
            for (int i = 0; i < sacc[j].num_elements; i++)
                sacc[j].x[i] = wmma::__float_to_tf32(__expf(sacc[j].x[i]));
            wmma::store_matrix_sync(s_sp + rt * 16 * LD + (ct0 + j) * 16, sacc[j], LD,
                                    wmma::mem_row_major);
        }
        // only the pair sharing row tile rt exchanges P
        pair_bar(rt + 1);

        // ---- O += P @ V ;  l += P @ ones ----
        float* vbuf = s_v + cur * 64 * LD;
#pragma unroll
        for (int ks = 0; ks < 8; ks++) {
            wmma::fragment<wmma::matrix_a, 16, 16, 8, wmma::precision::tf32, wmma::row_major> af;
            wmma::load_matrix_sync(af, s_sp + rt * 16 * LD + ks * 8, LD);
#pragma unroll
            for (int j = 0; j < 2; j++) {
                wmma::fragment<wmma::matrix_b, 16, 16, 8, wmma::precision::tf32, wmma::row_major> bf;
                wmma::load_matrix_sync(bf, vbuf + ks * 8 * LD + (ct0 + j) * 16, LD);
                wmma::mma_sync(oacc[j], af, bf, oacc[j]);
            }
            if (ct0 == 0) wmma::mma_sync(lacc, af, onesf, lacc);
        }
        // next iteration's top __syncthreads protects s_sp and K/V reuse
    }

    // ---- epilogue: O to s_sp, l (col 0) to s_k rows ----
    __syncthreads();
#pragma unroll
    for (int j = 0; j < 2; j++)
        wmma::store_matrix_sync(s_sp + rt * 16 * LD + (ct0 + j) * 16, oacc[j], LD,
                                wmma::mem_row_major);
    if (ct0 == 0)
        wmma::store_matrix_sync(s_k + rt * 16 * LD, lacc, LD, wmma::mem_row_major);
    __syncthreads();

    for (int idx = tid; idx < 64 * 64; idx += 256) {
        int row = idx >> 6, col = idx & 63;
        out[(size_t)(b * NN + q0 + row) * HH + col] =
            s_sp[row * LD + col] / s_k[row * LD];
    }
}

// ---------------------------------------------------------------------------
extern "C" void kernel_launch(void* const* d_in, const int* in_sizes, int n_in,
                              void* d_out, int out_size)
{
    const float* x  = (const float*)d_in[0];
    const float* Wq = (const float*)d_in[1];
    const float* bq = (const float*)d_in[2];
    const float* Wk = (const float*)d_in[3];
    const float* bk = (const float*)d_in[4];
    const float* Wv = (const float*)d_in[5];
    const float* bv = (const float*)d_in[6];
    float* out = (float*)d_out;

    const int smem_proj = (64 * LD + 3 * 64 * LD) * (int)sizeof(float);          // 69632
    const int smem_attn = (5 * 64 * LD + 128 + 32) * (int)sizeof(float);         // ~87.7KB

    (void)cudaFuncSetAttribute(proj_kernel, cudaFuncAttributeMaxDynamicSharedMemorySize, smem_proj);
    (void)cudaFuncSetAttribute(attn_kernel, cudaFuncAttributeMaxDynamicSharedMemorySize, smem_attn);

    proj_kernel<<<(BB * NN) / 64, 384, smem_proj>>>(x, Wq, bq, Wk, bk, Wv, bv);
    attn_kernel<<<dim3(NN / 64, BB), 256, smem_attn>>>(out);
}

// round 6
// speedup vs baseline: 1.3716x; 1.1112x over previous
#include <cuda_runtime.h>
#include <cuda_bf16.h>
#include <cstdint>
#include <mma.h>

using namespace nvcuda;

// Problem constants
#define BB 8
#define NN 4096
#define DD 768
#define HH 64

// Shared-memory leading dim (floats): 68 keeps float4 alignment and staggers banks.
#define LD 68

// Device scratch for Q, K, V projections (fp32 values pre-rounded to tf32).
__device__ float g_q[BB * NN * HH];
__device__ float g_k[BB * NN * HH];
__device__ float g_v[BB * NN * HH];

// ---------------------------------------------------------------------------
// cp.async helpers
// ---------------------------------------------------------------------------
__device__ __forceinline__ void cp_async16(float* smem_dst, const float* gmem_src) {
    unsigned s = (unsigned)__cvta_generic_to_shared(smem_dst);
    asm volatile("cp.async.cg.shared.global [%0], [%1], 16;\n" :: "r"(s), "l"(gmem_src));
}
__device__ __forceinline__ void cp_async_commit() {
    asm volatile("cp.async.commit_group;\n");
}

// ---------------------------------------------------------------------------
// Kernel 1: fused Q/K/V projection (unchanged from R5 — known good).
// Epilogue pre-rounds outputs to tf32 so attn skips all cvt loops.
// ---------------------------------------------------------------------------
__global__ void proj_kernel(const float* __restrict__ x,
                            const float* __restrict__ Wq, const float* __restrict__ bq,
                            const float* __restrict__ Wk, const float* __restrict__ bk,
                            const float* __restrict__ Wv, const float* __restrict__ bv)
{
    extern __shared__ float sm[];
    float* s_x = sm;             // [64][LD]
    float* s_w = sm + 64 * LD;   // [3][64][LD], reused as output staging

    const int tid  = threadIdx.x;
    const int warp = tid >> 5;
    const int r0   = blockIdx.x * 64;

    const float* Ws[3] = {Wq, Wk, Wv};

    wmma::fragment<wmma::accumulator, 16, 16, 8, float> acc[4];
#pragma unroll
    for (int i = 0; i < 4; i++) wmma::fill_fragment(acc[i], 0.0f);

    const int m  = warp >> 2;   // 0..2 : which projection
    const int ct = warp & 3;    // 0..3 : which 16-col strip

    for (int kc = 0; kc < DD; kc += 64) {
        for (int idx = tid; idx < 64 * 16; idx += 384) {
            int row = idx >> 4, c4 = idx & 15;
            float4 v4 = *(const float4*)(x + (size_t)(r0 + row) * DD + kc + c4 * 4);
            *(float4*)(s_x + row * LD + c4 * 4) = v4;
        }
        for (int idx = tid; idx < 3 * 64 * 16; idx += 384) {
            int mm = idx >> 10;
            int rem = idx & 1023;
            int k = rem >> 4, n4 = rem & 15;
            float4 v4 = *(const float4*)(Ws[mm] + (size_t)(kc + k) * HH + n4 * 4);
            *(float4*)(s_w + mm * (64 * LD) + k * LD + n4 * 4) = v4;
        }
        __syncthreads();

#pragma unroll
        for (int ks = 0; ks < 8; ks++) {
            wmma::fragment<wmma::matrix_b, 16, 16, 8, wmma::precision::tf32, wmma::row_major> bf;
            wmma::load_matrix_sync(bf, s_w + m * (64 * LD) + ks * 8 * LD + ct * 16, LD);
#pragma unroll
            for (int i = 0; i < bf.num_elements; i++) bf.x[i] = wmma::__float_to_tf32(bf.x[i]);
#pragma unroll
            for (int rt = 0; rt < 4; rt++) {
                wmma::fragment<wmma::matrix_a, 16, 16, 8, wmma::precision::tf32, wmma::row_major> af;
                wmma::load_matrix_sync(af, s_x + rt * 16 * LD + ks * 8, LD);
#pragma unroll
                for (int i = 0; i < af.num_elements; i++) af.x[i] = wmma::__float_to_tf32(af.x[i]);
                wmma::mma_sync(acc[rt], af, bf, acc[rt]);
            }
        }
        __syncthreads();
    }

#pragma unroll
    for (int rt = 0; rt < 4; rt++)
        wmma::store_matrix_sync(s_w + m * (64 * LD) + rt * 16 * LD + ct * 16, acc[rt], LD,
                                wmma::mem_row_major);
    __syncthreads();

    const float* bs[3] = {bq, bk, bv};
    float* outs[3] = {g_q, g_k, g_v};
    for (int mm = 0; mm < 3; mm++) {
        for (int idx = tid; idx < 64 * 64; idx += 384) {
            int row = idx >> 6, col = idx & 63;
            outs[mm][(size_t)(r0 + row) * HH + col] =
                wmma::__float_to_tf32(s_w[mm * (64 * LD) + row * LD + col] + bs[mm][col]);
        }
    }
}

// ---------------------------------------------------------------------------
// Kernel 2: flash attention, warp-private P, 128 q-rows per CTA.
// 8 warps, each owns a 16-row tile: computes its full 16x64 S strip, exps in
// registers, stores P to its PRIVATE smem slice, reloads for PV — no barrier
// for P at all. Single __syncthreads per key block (K/V double buffer).
// ---------------------------------------------------------------------------
__global__ void __launch_bounds__(256, 2) attn_kernel(float* __restrict__ out)
{
    extern __shared__ float sm[];
    float* s_k    = sm;                    // [2][64][LD]
    float* s_v    = s_k + 2 * 64 * LD;     // [2][64][LD]
    float* s_p    = s_v + 2 * 64 * LD;     // [128][LD]  Q staging -> P (warp-private) -> O
    float* s_l    = s_p + 128 * LD;        // [128]
    float* s_ones = s_l + 128;             // [8][16] ones B-tile (col 0 = 1)

    const int tid  = threadIdx.x;
    const int warp = tid >> 5;
    const int lane = tid & 31;
    const int b    = blockIdx.y;
    const int q0   = blockIdx.x * 128;
    const float scale = 0.125f;            // 1/sqrt(64), exact power of two

    // ---- stage Q (pre-scaled; tf32-preserving) into s_p ----
    for (int idx = tid; idx < 128 * 16; idx += 256) {
        int row = idx >> 4, c4 = idx & 15;
        float4 v4 = *(const float4*)(g_q + (size_t)(b * NN + q0 + row) * HH + c4 * 4);
        v4.x *= scale; v4.y *= scale; v4.z *= scale; v4.w *= scale;
        *(float4*)(s_p + row * LD + c4 * 4) = v4;
    }
    if (tid < 128) s_ones[tid] = ((tid & 15) == 0) ? 1.0f : 0.0f;
    __syncthreads();

    // ---- per-warp persistent fragments (own 16-row slice; already tf32) ----
    float* pslc = s_p + warp * 16 * LD;    // this warp's private slice
    wmma::fragment<wmma::matrix_a, 16, 16, 8, wmma::precision::tf32, wmma::row_major> qf[8];
#pragma unroll
    for (int ks = 0; ks < 8; ks++)
        wmma::load_matrix_sync(qf[ks], pslc + ks * 8, LD);

    wmma::fragment<wmma::matrix_b, 16, 16, 8, wmma::precision::tf32, wmma::row_major> onesf;
    wmma::load_matrix_sync(onesf, s_ones, 16);

    wmma::fragment<wmma::accumulator, 16, 16, 8, float> oacc[4], lacc;
#pragma unroll
    for (int j = 0; j < 4; j++) wmma::fill_fragment(oacc[j], 0.0f);
    wmma::fill_fragment(lacc, 0.0f);

    // ---- prologue: async-load K/V block 0 into buffer 0 ----
    const float* gk = g_k + (size_t)b * NN * HH;
    const float* gv = g_v + (size_t)b * NN * HH;
    const int lrow = tid >> 2;             // 4 float4 per thread per tile
    const int lc4  = (tid & 3) * 4;
#pragma unroll
    for (int u = 0; u < 4; u++) {
        cp_async16(s_k + lrow * LD + (lc4 + u) * 4, gk + (size_t)lrow * HH + (lc4 + u) * 4);
        cp_async16(s_v + lrow * LD + (lc4 + u) * 4, gv + (size_t)lrow * HH + (lc4 + u) * 4);
    }
    cp_async_commit();

    for (int kb = 0; kb < NN / 64; kb++) {
        const int cur = kb & 1;
        const int nxt = cur ^ 1;

        // one barrier per key block: cur K/V visible + prev iter finished
        asm volatile("cp.async.wait_group 0;\n");
        __syncthreads();

        if (kb < NN / 64 - 1) {
            const int k0n = (kb + 1) * 64;
#pragma unroll
            for (int u = 0; u < 4; u++) {
                cp_async16(s_k + nxt * 64 * LD + lrow * LD + (lc4 + u) * 4,
                           gk + (size_t)(k0n + lrow) * HH + (lc4 + u) * 4);
                cp_async16(s_v + nxt * 64 * LD + lrow * LD + (lc4 + u) * 4,
                           gv + (size_t)(k0n + lrow) * HH + (lc4 + u) * 4);
            }
            cp_async_commit();
        }

        // ---- S = Q @ K^T for this warp's 16 rows x all 64 cols,
        //      in two halves of 2 tiles to cap register pressure ----
        float* kbuf = s_k + cur * 64 * LD;
#pragma unroll
        for (int h = 0; h < 2; h++) {
            wmma::fragment<wmma::accumulator, 16, 16, 8, float> sacc[2];
            wmma::fill_fragment(sacc[0], 0.0f);
            wmma::fill_fragment(sacc[1], 0.0f);
#pragma unroll
            for (int ks = 0; ks < 8; ks++) {
#pragma unroll
                for (int j = 0; j < 2; j++) {
                    wmma::fragment<wmma::matrix_b, 16, 16, 8, wmma::precision::tf32, wmma::col_major> bf;
                    wmma::load_matrix_sync(bf, kbuf + (h * 2 + j) * 16 * LD + ks * 8, LD);
                    wmma::mma_sync(sacc[j], qf[ks], bf, sacc[j]);
                }
            }
            // P = exp(S), rounded to tf32; store into WARP-PRIVATE slice
#pragma unroll
            for (int j = 0; j < 2; j++) {
#pragma unroll
                for (int i = 0; i < sacc[j].num_elements; i++)
                    sacc[j].x[i] = wmma::__float_to_tf32(__expf(sacc[j].x[i]));
                wmma::store_matrix_sync(pslc + (h * 2 + j) * 16, sacc[j], LD,
                                        wmma::mem_row_major);
            }
        }
        // same-warp store->load: no barrier needed

        // ---- O += P @ V ;  l += P @ ones ----
        float* vbuf = s_v + cur * 64 * LD;
#pragma unroll
        for (int ks = 0; ks < 8; ks++) {
            wmma::fragment<wmma::matrix_a, 16, 16, 8, wmma::precision::tf32, wmma::row_major> af;
            wmma::load_matrix_sync(af, pslc + ks * 8, LD);
#pragma unroll
            for (int j = 0; j < 4; j++) {
                wmma::fragment<wmma::matrix_b, 16, 16, 8, wmma::precision::tf32, wmma::row_major> bf;
                wmma::load_matrix_sync(bf, vbuf + ks * 8 * LD + j * 16, LD);
                wmma::mma_sync(oacc[j], af, bf, oacc[j]);
            }
            wmma::mma_sync(lacc, af, onesf, lacc);
        }
        // next iteration's top __syncthreads protects K/V buffers
    }

    // ---- epilogue (warp-private slice): l first, then O over it ----
    wmma::store_matrix_sync(pslc, lacc, LD, wmma::mem_row_major);
    __syncwarp();
    if (lane < 16) s_l[warp * 16 + lane] = pslc[lane * LD];
    __syncwarp();
#pragma unroll
    for (int j = 0; j < 4; j++)
        wmma::store_matrix_sync(pslc + j * 16, oacc[j], LD, wmma::mem_row_major);
    __syncthreads();

    for (int idx = tid; idx < 128 * 64; idx += 256) {
        int row = idx >> 6, col = idx & 63;
        out[(size_t)(b * NN + q0 + row) * HH + col] =
            s_p[row * LD + col] / s_l[row];
    }
}

// ---------------------------------------------------------------------------
extern "C" void kernel_launch(void* const* d_in, const int* in_sizes, int n_in,
                              void* d_out, int out_size)
{
    const float* x  = (const float*)d_in[0];
    const float* Wq = (const float*)d_in[1];
    const float* bq = (const float*)d_in[2];
    const float* Wk = (const float*)d_in[3];
    const float* bk = (const float*)d_in[4];
    const float* Wv = (const float*)d_in[5];
    const float* bv = (const float*)d_in[6];
    float* out = (float*)d_out;

    const int smem_proj = (64 * LD + 3 * 64 * LD) * (int)sizeof(float);          // 69632
    const int smem_attn = (4 * 64 * LD + 128 * LD + 128 + 128) * (int)sizeof(float); // ~105KB

    (void)cudaFuncSetAttribute(proj_kernel, cudaFuncAttributeMaxDynamicSharedMemorySize, smem_proj);
    (void)cudaFuncSetAttribute(attn_kernel, cudaFuncAttributeMaxDynamicSharedMemorySize, smem_attn);

    proj_kernel<<<(BB * NN) / 64, 384, smem_proj>>>(x, Wq, bq, Wk, bk, Wv, bv);
    attn_kernel<<<dim3(NN / 128, BB), 256, smem_attn>>>(out);
}

// round 7
// speedup vs baseline: 2.3980x; 1.7483x over previous
#include <cuda_runtime.h>
#include <cuda_bf16.h>
#include <cstdint>
#include <mma.h>

using namespace nvcuda;

// Problem constants
#define BB 8
#define NN 4096
#define DD 768
#define HH 64

// Shared-memory leading dim (floats): 68 keeps float4 alignment and staggers banks.
#define LD 68

// Device scratch for Q, K, V projections (fp32 values pre-rounded to tf32).
__device__ float g_q[BB * NN * HH];
__device__ float g_k[BB * NN * HH];
__device__ float g_v[BB * NN * HH];

// ---------------------------------------------------------------------------
// helpers
// ---------------------------------------------------------------------------
__device__ __forceinline__ void cp_async16(float* smem_dst, const float* gmem_src) {
    unsigned s = (unsigned)__cvta_generic_to_shared(smem_dst);
    asm volatile("cp.async.cg.shared.global [%0], [%1], 16;\n" :: "r"(s), "l"(gmem_src));
}
__device__ __forceinline__ void cp_async_commit() {
    asm volatile("cp.async.commit_group;\n");
}
__device__ __forceinline__ float rtf32(float f) {
    unsigned u;
    asm("cvt.rna.tf32.f32 %0, %1;" : "=r"(u) : "f"(f));
    return __uint_as_float(u);
}
// d = a @ b + c, m16n8k8 tf32. d may alias c.
__device__ __forceinline__ void mma16n8k8(float* d, const unsigned* a, const unsigned* b2,
                                          const float* c) {
    asm volatile(
        "mma.sync.aligned.m16n8k8.row.col.f32.tf32.tf32.f32 "
        "{%0,%1,%2,%3}, {%4,%5,%6,%7}, {%8,%9}, {%10,%11,%12,%13};\n"
        : "=f"(d[0]), "=f"(d[1]), "=f"(d[2]), "=f"(d[3])
        : "r"(a[0]), "r"(a[1]), "r"(a[2]), "r"(a[3]),
          "r"(b2[0]), "r"(b2[1]),
          "f"(c[0]), "f"(c[1]), "f"(c[2]), "f"(c[3]));
}

// ---------------------------------------------------------------------------
// Kernel 1: fused Q/K/V projection. tf32 rounding moved to smem-store time;
// inner-loop cvt loops removed (identical math, far fewer instructions).
// ---------------------------------------------------------------------------
__global__ void proj_kernel(const float* __restrict__ x,
                            const float* __restrict__ Wq, const float* __restrict__ bq,
                            const float* __restrict__ Wk, const float* __restrict__ bk,
                            const float* __restrict__ Wv, const float* __restrict__ bv)
{
    extern __shared__ float sm[];
    float* s_x = sm;             // [64][LD]
    float* s_w = sm + 64 * LD;   // [3][64][LD], reused as output staging

    const int tid  = threadIdx.x;
    const int warp = tid >> 5;
    const int r0   = blockIdx.x * 64;

    const float* Ws[3] = {Wq, Wk, Wv};

    wmma::fragment<wmma::accumulator, 16, 16, 8, float> acc[4];
#pragma unroll
    for (int i = 0; i < 4; i++) wmma::fill_fragment(acc[i], 0.0f);

    const int m  = warp >> 2;   // 0..2 : which projection
    const int ct = warp & 3;    // 0..3 : which 16-col strip

    for (int kc = 0; kc < DD; kc += 64) {
        for (int idx = tid; idx < 64 * 16; idx += 384) {
            int row = idx >> 4, c4 = idx & 15;
            float4 v4 = *(const float4*)(x + (size_t)(r0 + row) * DD + kc + c4 * 4);
            v4.x = rtf32(v4.x); v4.y = rtf32(v4.y); v4.z = rtf32(v4.z); v4.w = rtf32(v4.w);
            *(float4*)(s_x + row * LD + c4 * 4) = v4;
        }
        for (int idx = tid; idx < 3 * 64 * 16; idx += 384) {
            int mm = idx >> 10;
            int rem = idx & 1023;
            int k = rem >> 4, n4 = rem & 15;
            float4 v4 = *(const float4*)(Ws[mm] + (size_t)(kc + k) * HH + n4 * 4);
            v4.x = rtf32(v4.x); v4.y = rtf32(v4.y); v4.z = rtf32(v4.z); v4.w = rtf32(v4.w);
            *(float4*)(s_w + mm * (64 * LD) + k * LD + n4 * 4) = v4;
        }
        __syncthreads();

#pragma unroll
        for (int ks = 0; ks < 8; ks++) {
            wmma::fragment<wmma::matrix_b, 16, 16, 8, wmma::precision::tf32, wmma::row_major> bf;
            wmma::load_matrix_sync(bf, s_w + m * (64 * LD) + ks * 8 * LD + ct * 16, LD);
#pragma unroll
            for (int rt = 0; rt < 4; rt++) {
                wmma::fragment<wmma::matrix_a, 16, 16, 8, wmma::precision::tf32, wmma::row_major> af;
                wmma::load_matrix_sync(af, s_x + rt * 16 * LD + ks * 8, LD);
                wmma::mma_sync(acc[rt], af, bf, acc[rt]);
            }
        }
        __syncthreads();
    }

#pragma unroll
    for (int rt = 0; rt < 4; rt++)
        wmma::store_matrix_sync(s_w + m * (64 * LD) + rt * 16 * LD + ct * 16, acc[rt], LD,
                                wmma::mem_row_major);
    __syncthreads();

    const float* bs[3] = {bq, bk, bv};
    float* outs[3] = {g_q, g_k, g_v};
    for (int mm = 0; mm < 3; mm++) {
        for (int idx = tid; idx < 64 * 64; idx += 384) {
            int row = idx >> 6, col = idx & 63;
            outs[mm][(size_t)(r0 + row) * HH + col] =
                rtf32(s_w[mm * (64 * LD) + row * LD + col] + bs[mm][col]);
        }
    }
}

// ---------------------------------------------------------------------------
// Kernel 2: flash attention with raw mma.m16n8k8 and P entirely in registers.
// 8 warps x 16 q-rows = 128 rows/CTA. S accumulates in C-fragments, exp in
// registers, C reused as A for PV via {c0,c2,c1,c3} permutation with
// sigma-permuted V row loads. l via constant-ones B fragment. smem = K/V only.
// ---------------------------------------------------------------------------
__global__ void __launch_bounds__(256, 2) attn_kernel(float* __restrict__ out)
{
    extern __shared__ float sm[];
    float* s_k = sm;                    // [2][64][LD]
    float* s_v = s_k + 2 * 64 * LD;     // [2][64][LD]

    const int tid  = threadIdx.x;
    const int warp = tid >> 5;
    const int lane = tid & 31;
    const int g    = lane >> 2;         // group id 0..7 (row within tile)
    const int tig  = lane & 3;          // thread in group
    const int b    = blockIdx.y;
    const int q0   = blockIdx.x * 128;
    const float scale = 0.125f;         // 1/sqrt(64), exact power of two

    // ---- persistent Q A-fragments (global values already tf32; *0.125 exact) ----
    // A layout m16n8k8: a0=(g,tig) a1=(g+8,tig) a2=(g,tig+4) a3=(g+8,tig+4)
    const float* qbase = g_q + (size_t)(b * NN + q0 + warp * 16) * HH;
    unsigned qa[8][4];
#pragma unroll
    for (int ks = 0; ks < 8; ks++) {
        qa[ks][0] = __float_as_uint(qbase[(size_t)g * HH + ks * 8 + tig] * scale);
        qa[ks][1] = __float_as_uint(qbase[(size_t)(g + 8) * HH + ks * 8 + tig] * scale);
        qa[ks][2] = __float_as_uint(qbase[(size_t)g * HH + ks * 8 + tig + 4] * scale);
        qa[ks][3] = __float_as_uint(qbase[(size_t)(g + 8) * HH + ks * 8 + tig + 4] * scale);
    }

    // ones B fragment: col 0 = 1 (B rows are keys; permutation of all-ones is all-ones)
    unsigned onesb2[2];
    onesb2[0] = onesb2[1] = (g == 0) ? 0x3f800000u : 0u;

    float oacc[8][4];
#pragma unroll
    for (int j = 0; j < 8; j++)
#pragma unroll
        for (int i = 0; i < 4; i++) oacc[j][i] = 0.0f;
    float lacc[4] = {0.f, 0.f, 0.f, 0.f};

    // ---- prologue: async-load K/V block 0 into buffer 0 ----
    const float* gk = g_k + (size_t)b * NN * HH;
    const float* gv = g_v + (size_t)b * NN * HH;
    const int lrow = tid >> 2;          // 4 float4 per thread per tile
    const int lc4  = (tid & 3) * 4;
#pragma unroll
    for (int u = 0; u < 4; u++) {
        cp_async16(s_k + lrow * LD + (lc4 + u) * 4, gk + (size_t)lrow * HH + (lc4 + u) * 4);
        cp_async16(s_v + lrow * LD + (lc4 + u) * 4, gv + (size_t)lrow * HH + (lc4 + u) * 4);
    }
    cp_async_commit();

    for (int kb = 0; kb < NN / 64; kb++) {
        const int cur = kb & 1;
        const int nxt = cur ^ 1;

        asm volatile("cp.async.wait_group 0;\n");
        __syncthreads();

        if (kb < NN / 64 - 1) {
            const int k0n = (kb + 1) * 64;
#pragma unroll
            for (int u = 0; u < 4; u++) {
                cp_async16(s_k + nxt * 64 * LD + lrow * LD + (lc4 + u) * 4,
                           gk + (size_t)(k0n + lrow) * HH + (lc4 + u) * 4);
                cp_async16(s_v + nxt * 64 * LD + lrow * LD + (lc4 + u) * 4,
                           gv + (size_t)(k0n + lrow) * HH + (lc4 + u) * 4);
            }
            cp_async_commit();
        }

        const float* kbuf = s_k + cur * 64 * LD;
        const float* vbuf = s_v + cur * 64 * LD;

#pragma unroll
        for (int h = 0; h < 2; h++) {           // 32 keys per half (register cap)
            const int kc0 = h * 32;

            // ---- S = Q @ K^T : 4 n-tiles of 8 keys ----
            float sacc[4][4];
#pragma unroll
            for (int c = 0; c < 4; c++)
#pragma unroll
                for (int i = 0; i < 4; i++) sacc[c][i] = 0.0f;

#pragma unroll
            for (int ks = 0; ks < 8; ks++) {
#pragma unroll
                for (int c = 0; c < 4; c++) {
                    // B (k8 x n8, col-major): b0=(row tig -> d, col g -> key)
                    const float* kp = kbuf + (size_t)(kc0 + c * 8 + g) * LD + ks * 8;
                    unsigned kb2[2];
                    kb2[0] = __float_as_uint(kp[tig]);
                    kb2[1] = __float_as_uint(kp[tig + 4]);
                    mma16n8k8(sacc[c], qa[ks], kb2, sacc[c]);
                }
            }

            // ---- P = exp(S) in registers; repack C->A ({c0,c2,c1,c3}) ----
            unsigned pa[4][4];
#pragma unroll
            for (int c = 0; c < 4; c++) {
                float e0 = __expf(sacc[c][0]);
                float e1 = __expf(sacc[c][1]);
                float e2 = __expf(sacc[c][2]);
                float e3 = __expf(sacc[c][3]);
                pa[c][0] = __float_as_uint(rtf32(e0));
                pa[c][1] = __float_as_uint(rtf32(e2));
                pa[c][2] = __float_as_uint(rtf32(e1));
                pa[c][3] = __float_as_uint(rtf32(e3));
            }

            // ---- l += P @ ones ----
#pragma unroll
            for (int c = 0; c < 4; c++)
                mma16n8k8(lacc, pa[c], onesb2, lacc);

            // ---- O += P @ V  (V rows sigma-permuted: 2*tig, 2*tig+1) ----
#pragma unroll
            for (int j = 0; j < 8; j++) {
#pragma unroll
                for (int c = 0; c < 4; c++) {
                    const float* vp = vbuf + (size_t)(kc0 + c * 8) * LD + j * 8 + g;
                    unsigned vb2[2];
                    vb2[0] = __float_as_uint(vp[(size_t)(2 * tig) * LD]);
                    vb2[1] = __float_as_uint(vp[(size_t)(2 * tig + 1) * LD]);
                    mma16n8k8(oacc[j], pa[c], vb2, oacc[j]);
                }
            }
        }
        // next iteration's top __syncthreads protects K/V buffers
    }

    // ---- epilogue: l lives in col 0 (threads with tig==0); broadcast, divide, store ----
    float lg  = __shfl_sync(0xffffffffu, lacc[0], lane & ~3);
    float lg8 = __shfl_sync(0xffffffffu, lacc[2], lane & ~3);
    float inv0 = 1.0f / lg;
    float inv8 = 1.0f / lg8;

    float* orow0 = out + (size_t)(b * NN + q0 + warp * 16 + g) * HH;
    float* orow8 = out + (size_t)(b * NN + q0 + warp * 16 + g + 8) * HH;
#pragma unroll
    for (int j = 0; j < 8; j++) {
        float2 v0 = make_float2(oacc[j][0] * inv0, oacc[j][1] * inv0);
        float2 v8 = make_float2(oacc[j][2] * inv8, oacc[j][3] * inv8);
        *(float2*)(orow0 + j * 8 + 2 * tig) = v0;
        *(float2*)(orow8 + j * 8 + 2 * tig) = v8;
    }
}

// ---------------------------------------------------------------------------
extern "C" void kernel_launch(void* const* d_in, const int* in_sizes, int n_in,
                              void* d_out, int out_size)
{
    const float* x  = (const float*)d_in[0];
    const float* Wq = (const float*)d_in[1];
    const float* bq = (const float*)d_in[2];
    const float* Wk = (const float*)d_in[3];
    const float* bk = (const float*)d_in[4];
    const float* Wv = (const float*)d_in[5];
    const float* bv = (const float*)d_in[6];
    float* out = (float*)d_out;

    const int smem_proj = (64 * LD + 3 * 64 * LD) * (int)sizeof(float);   // 69632
    const int smem_attn = (4 * 64 * LD) * (int)sizeof(float);             // 69632

    (void)cudaFuncSetAttribute(proj_kernel, cudaFuncAttributeMaxDynamicSharedMemorySize, smem_proj);
    (void)cudaFuncSetAttribute(attn_kernel, cudaFuncAttributeMaxDynamicSharedMemorySize, smem_attn);

    proj_kernel<<<(BB * NN) / 64, 384, smem_proj>>>(x, Wq, bq, Wk, bk, Wv, bv);
    attn_kernel<<<dim3(NN / 128, BB), 256, smem_attn>>>(out);
}

// round 8
// speedup vs baseline: 3.1819x; 1.3269x over previous
#include <cuda_runtime.h>
#include <cuda_bf16.h>
#include <cstdint>
#include <mma.h>

// Problem constants
#define BB 8
#define NN 4096
#define DD 768
#define HH 64

// Shared-memory leading dim (floats): 68 keeps float4 alignment and staggers banks.
#define LD 68

// Device scratch for Q, K, V projections (fp32 values pre-rounded to tf32).
__device__ float g_q[BB * NN * HH];
__device__ float g_k[BB * NN * HH];
__device__ float g_v[BB * NN * HH];

// ---------------------------------------------------------------------------
// helpers
// ---------------------------------------------------------------------------
__device__ __forceinline__ void cp_async16(float* smem_dst, const float* gmem_src) {
    unsigned s = (unsigned)__cvta_generic_to_shared(smem_dst);
    asm volatile("cp.async.cg.shared.global [%0], [%1], 16;\n" :: "r"(s), "l"(gmem_src));
}
__device__ __forceinline__ void cp_async_commit() {
    asm volatile("cp.async.commit_group;\n");
}
__device__ __forceinline__ float rtf32(float f) {
    unsigned u;
    asm("cvt.rna.tf32.f32 %0, %1;" : "=r"(u) : "f"(f));
    return __uint_as_float(u);
}
// d = a @ b + c, m16n8k8 tf32. d may alias c.
__device__ __forceinline__ void mma16n8k8(float* d, const unsigned* a, const unsigned* b2,
                                          const float* c) {
    asm volatile(
        "mma.sync.aligned.m16n8k8.row.col.f32.tf32.tf32.f32 "
        "{%0,%1,%2,%3}, {%4,%5,%6,%7}, {%8,%9}, {%10,%11,%12,%13};\n"
        : "=f"(d[0]), "=f"(d[1]), "=f"(d[2]), "=f"(d[3])
        : "r"(a[0]), "r"(a[1]), "r"(a[2]), "r"(a[3]),
          "r"(b2[0]), "r"(b2[1]),
          "f"(c[0]), "f"(c[1]), "f"(c[2]), "f"(c[3]));
}

// ---------------------------------------------------------------------------
// Kernel 1: fused Q/K/V projection, raw-mma rewrite.
// 256 CTAs x 128 rows, 8 warps. Each warp: 16 rows x 192 cols = 24 C-frags.
// x double-buffered in smem via cp.async; W read directly from global
// (L2-resident) into B-fragments. One __syncthreads per 64-K chunk.
// ---------------------------------------------------------------------------
__global__ void __launch_bounds__(256, 2) proj_kernel(
    const float* __restrict__ x,
    const float* __restrict__ Wq, const float* __restrict__ bq,
    const float* __restrict__ Wk, const float* __restrict__ bk,
    const float* __restrict__ Wv, const float* __restrict__ bv)
{
    extern __shared__ float sm[];          // [2][128][LD]

    const int tid  = threadIdx.x;
    const int warp = tid >> 5;
    const int lane = tid & 31;
    const int g    = lane >> 2;            // 0..7
    const int tig  = lane & 3;             // 0..3
    const size_t row0 = (size_t)blockIdx.x * 128;

    const float* Ws[3] = {Wq, Wk, Wv};

    float cacc[24][4];
#pragma unroll
    for (int j = 0; j < 24; j++)
#pragma unroll
        for (int i = 0; i < 4; i++) cacc[j][i] = 0.0f;

    // prologue: chunk 0 of x into buffer 0
#pragma unroll
    for (int i = 0; i < 8; i++) {
        int idx = tid + i * 256;
        int row = idx >> 4, c4 = idx & 15;
        cp_async16(sm + row * LD + c4 * 4, x + (row0 + row) * DD + c4 * 4);
    }
    cp_async_commit();

    for (int kc = 0; kc < DD / 64; kc++) {
        const int cur = kc & 1;
        const int nxt = cur ^ 1;

        asm volatile("cp.async.wait_group 0;\n");
        __syncthreads();

        if (kc < DD / 64 - 1) {
#pragma unroll
            for (int i = 0; i < 8; i++) {
                int idx = tid + i * 256;
                int row = idx >> 4, c4 = idx & 15;
                cp_async16(sm + nxt * 128 * LD + row * LD + c4 * 4,
                           x + (row0 + row) * DD + (kc + 1) * 64 + c4 * 4);
            }
            cp_async_commit();
        }

        const float* xs = sm + cur * 128 * LD + warp * 16 * LD;
#pragma unroll
        for (int ks = 0; ks < 8; ks++) {
            unsigned a[4];
            a[0] = __float_as_uint(rtf32(xs[(size_t)g * LD + ks * 8 + tig]));
            a[1] = __float_as_uint(rtf32(xs[(size_t)(g + 8) * LD + ks * 8 + tig]));
            a[2] = __float_as_uint(rtf32(xs[(size_t)g * LD + ks * 8 + tig + 4]));
            a[3] = __float_as_uint(rtf32(xs[(size_t)(g + 8) * LD + ks * 8 + tig + 4]));
#pragma unroll
            for (int j = 0; j < 24; j++) {
                const float* wp = Ws[j >> 3] +
                    (size_t)(kc * 64 + ks * 8 + tig) * HH + (j & 7) * 8 + g;
                unsigned b2[2];
                b2[0] = __float_as_uint(wp[0]);        // k = base+tig
                b2[1] = __float_as_uint(wp[4 * HH]);   // k = base+tig+4
                mma16n8k8(cacc[j], a, b2, cacc[j]);
            }
        }
    }

    // epilogue: bias add, round to tf32, float2 stores
    const float* bs[3] = {bq, bk, bv};
    float* outs[3] = {g_q, g_k, g_v};
#pragma unroll
    for (int j = 0; j < 24; j++) {
        int mm = j >> 3;
        int col = (j & 7) * 8 + 2 * tig;
        float b0 = bs[mm][col], b1 = bs[mm][col + 1];
        float* o0 = outs[mm] + (row0 + warp * 16 + g) * HH + col;
        float* o8 = outs[mm] + (row0 + warp * 16 + g + 8) * HH + col;
        float2 v0 = make_float2(rtf32(cacc[j][0] + b0), rtf32(cacc[j][1] + b1));
        float2 v8 = make_float2(rtf32(cacc[j][2] + b0), rtf32(cacc[j][3] + b1));
        *(float2*)o0 = v0;
        *(float2*)o8 = v8;
    }
}

// ---------------------------------------------------------------------------
// Kernel 2: flash attention with raw mma.m16n8k8 and P entirely in registers.
// (byte-identical to R7 — validated at 310us, rel_err 2.2e-4)
// ---------------------------------------------------------------------------
__global__ void __launch_bounds__(256, 2) attn_kernel(float* __restrict__ out)
{
    extern __shared__ float sm[];
    float* s_k = sm;                    // [2][64][LD]
    float* s_v = s_k + 2 * 64 * LD;     // [2][64][LD]

    const int tid  = threadIdx.x;
    const int warp = tid >> 5;
    const int lane = tid & 31;
    const int g    = lane >> 2;         // group id 0..7 (row within tile)
    const int tig  = lane & 3;          // thread in group
    const int b    = blockIdx.y;
    const int q0   = blockIdx.x * 128;
    const float scale = 0.125f;         // 1/sqrt(64), exact power of two

    // ---- persistent Q A-fragments (global values already tf32; *0.125 exact) ----
    const float* qbase = g_q + (size_t)(b * NN + q0 + warp * 16) * HH;
    unsigned qa[8][4];
#pragma unroll
    for (int ks = 0; ks < 8; ks++) {
        qa[ks][0] = __float_as_uint(qbase[(size_t)g * HH + ks * 8 + tig] * scale);
        qa[ks][1] = __float_as_uint(qbase[(size_t)(g + 8) * HH + ks * 8 + tig] * scale);
        qa[ks][2] = __float_as_uint(qbase[(size_t)g * HH + ks * 8 + tig + 4] * scale);
        qa[ks][3] = __float_as_uint(qbase[(size_t)(g + 8) * HH + ks * 8 + tig + 4] * scale);
    }

    unsigned onesb2[2];
    onesb2[0] = onesb2[1] = (g == 0) ? 0x3f800000u : 0u;

    float oacc[8][4];
#pragma unroll
    for (int j = 0; j < 8; j++)
#pragma unroll
        for (int i = 0; i < 4; i++) oacc[j][i] = 0.0f;
    float lacc[4] = {0.f, 0.f, 0.f, 0.f};

    const float* gk = g_k + (size_t)b * NN * HH;
    const float* gv = g_v + (size_t)b * NN * HH;
    const int lrow = tid >> 2;
    const int lc4  = (tid & 3) * 4;
#pragma unroll
    for (int u = 0; u < 4; u++) {
        cp_async16(s_k + lrow * LD + (lc4 + u) * 4, gk + (size_t)lrow * HH + (lc4 + u) * 4);
        cp_async16(s_v + lrow * LD + (lc4 + u) * 4, gv + (size_t)lrow * HH + (lc4 + u) * 4);
    }
    cp_async_commit();

    for (int kb = 0; kb < NN / 64; kb++) {
        const int cur = kb & 1;
        const int nxt = cur ^ 1;

        asm volatile("cp.async.wait_group 0;\n");
        __syncthreads();

        if (kb < NN / 64 - 1) {
            const int k0n = (kb + 1) * 64;
#pragma unroll
            for (int u = 0; u < 4; u++) {
                cp_async16(s_k + nxt * 64 * LD + lrow * LD + (lc4 + u) * 4,
                           gk + (size_t)(k0n + lrow) * HH + (lc4 + u) * 4);
                cp_async16(s_v + nxt * 64 * LD + lrow * LD + (lc4 + u) * 4,
                           gv + (size_t)(k0n + lrow) * HH + (lc4 + u) * 4);
            }
            cp_async_commit();
        }

        const float* kbuf = s_k + cur * 64 * LD;
        const float* vbuf = s_v + cur * 64 * LD;

#pragma unroll
        for (int h = 0; h < 2; h++) {
            const int kc0 = h * 32;

            float sacc[4][4];
#pragma unroll
            for (int c = 0; c < 4; c++)
#pragma unroll
                for (int i = 0; i < 4; i++) sacc[c][i] = 0.0f;

#pragma unroll
            for (int ks = 0; ks < 8; ks++) {
#pragma unroll
                for (int c = 0; c < 4; c++) {
                    const float* kp = kbuf + (size_t)(kc0 + c * 8 + g) * LD + ks * 8;
                    unsigned kb2[2];
                    kb2[0] = __float_as_uint(kp[tig]);
                    kb2[1] = __float_as_uint(kp[tig + 4]);
                    mma16n8k8(sacc[c], qa[ks], kb2, sacc[c]);
                }
            }

            unsigned pa[4][4];
#pragma unroll
            for (int c = 0; c < 4; c++) {
                float e0 = __expf(sacc[c][0]);
                float e1 = __expf(sacc[c][1]);
                float e2 = __expf(sacc[c][2]);
                float e3 = __expf(sacc[c][3]);
                pa[c][0] = __float_as_uint(rtf32(e0));
                pa[c][1] = __float_as_uint(rtf32(e2));
                pa[c][2] = __float_as_uint(rtf32(e1));
                pa[c][3] = __float_as_uint(rtf32(e3));
            }

#pragma unroll
            for (int c = 0; c < 4; c++)
                mma16n8k8(lacc, pa[c], onesb2, lacc);

#pragma unroll
            for (int j = 0; j < 8; j++) {
#pragma unroll
                for (int c = 0; c < 4; c++) {
                    const float* vp = vbuf + (size_t)(kc0 + c * 8) * LD + j * 8 + g;
                    unsigned vb2[2];
                    vb2[0] = __float_as_uint(vp[(size_t)(2 * tig) * LD]);
                    vb2[1] = __float_as_uint(vp[(size_t)(2 * tig + 1) * LD]);
                    mma16n8k8(oacc[j], pa[c], vb2, oacc[j]);
                }
            }
        }
    }

    float lg  = __shfl_sync(0xffffffffu, lacc[0], lane & ~3);
    float lg8 = __shfl_sync(0xffffffffu, lacc[2], lane & ~3);
    float inv0 = 1.0f / lg;
    float inv8 = 1.0f / lg8;

    float* orow0 = out + (size_t)(b * NN + q0 + warp * 16 + g) * HH;
    float* orow8 = out + (size_t)(b * NN + q0 + warp * 16 + g + 8) * HH;
#pragma unroll
    for (int j = 0; j < 8; j++) {
        float2 v0 = make_float2(oacc[j][0] * inv0, oacc[j][1] * inv0);
        float2 v8 = make_float2(oacc[j][2] * inv8, oacc[j][3] * inv8);
        *(float2*)(orow0 + j * 8 + 2 * tig) = v0;
        *(float2*)(orow8 + j * 8 + 2 * tig) = v8;
    }
}

// ---------------------------------------------------------------------------
extern "C" void kernel_launch(void* const* d_in, const int* in_sizes, int n_in,
                              void* d_out, int out_size)
{
    const float* x  = (const float*)d_in[0];
    const float* Wq = (const float*)d_in[1];
    const float* bq = (const float*)d_in[2];
    const float* Wk = (const float*)d_in[3];
    const float* bk = (const float*)d_in[4];
    const float* Wv = (const float*)d_in[5];
    const float* bv = (const float*)d_in[6];
    float* out = (float*)d_out;

    const int smem_proj = (2 * 128 * LD) * (int)sizeof(float);            // 69632
    const int smem_attn = (4 * 64 * LD) * (int)sizeof(float);             // 69632

    (void)cudaFuncSetAttribute(proj_kernel, cudaFuncAttributeMaxDynamicSharedMemorySize, smem_proj);
    (void)cudaFuncSetAttribute(attn_kernel, cudaFuncAttributeMaxDynamicSharedMemorySize, smem_attn);

    proj_kernel<<<(BB * NN) / 128, 256, smem_proj>>>(x, Wq, bq, Wk, bk, Wv, bv);
    attn_kernel<<<dim3(NN / 128, BB), 256, smem_attn>>>(out);
}

// round 9
// speedup vs baseline: 4.8051x; 1.5101x over previous
#include <cuda_runtime.h>
#include <cuda_fp16.h>
#include <cstdint>
#include <mma.h>

// Problem constants
#define BB 8
#define NN 4096
#define DD 768
#define HH 64

// proj smem leading dim (floats)
#define LD 68
// attn smem leading dim (halves): 72 -> bank = 4g+tig, conflict-free
#define LDH 72
#define TILEH (64 * LDH)

// Device scratch: fp16 projections. Q has 1/8 scale pre-folded. V stored transposed [b][d][n].
__device__ __half g_q[BB * NN * HH];
__device__ __half g_k[BB * NN * HH];
__device__ __half g_vT[BB * HH * NN];

// ---------------------------------------------------------------------------
// helpers
// ---------------------------------------------------------------------------
__device__ __forceinline__ void cp_async16(void* smem_dst, const void* gmem_src) {
    unsigned s = (unsigned)__cvta_generic_to_shared(smem_dst);
    asm volatile("cp.async.cg.shared.global [%0], [%1], 16;\n" :: "r"(s), "l"(gmem_src));
}
__device__ __forceinline__ void cp_async_commit() {
    asm volatile("cp.async.commit_group;\n");
}
__device__ __forceinline__ float rtf32(float f) {
    unsigned u;
    asm("cvt.rna.tf32.f32 %0, %1;" : "=r"(u) : "f"(f));
    return __uint_as_float(u);
}
// tf32 m16n8k8 (proj)
__device__ __forceinline__ void mma16n8k8(float* d, const unsigned* a, const unsigned* b2,
                                          const float* c) {
    asm volatile(
        "mma.sync.aligned.m16n8k8.row.col.f32.tf32.tf32.f32 "
        "{%0,%1,%2,%3}, {%4,%5,%6,%7}, {%8,%9}, {%10,%11,%12,%13};\n"
        : "=f"(d[0]), "=f"(d[1]), "=f"(d[2]), "=f"(d[3])
        : "r"(a[0]), "r"(a[1]), "r"(a[2]), "r"(a[3]),
          "r"(b2[0]), "r"(b2[1]),
          "f"(c[0]), "f"(c[1]), "f"(c[2]), "f"(c[3]));
}
// f16 m16n8k16, f32 accumulate (attn)
__device__ __forceinline__ void mmaf16(float* d, const unsigned* a, const unsigned* b2,
                                       const float* c) {
    asm volatile(
        "mma.sync.aligned.m16n8k16.row.col.f32.f16.f16.f32 "
        "{%0,%1,%2,%3}, {%4,%5,%6,%7}, {%8,%9}, {%10,%11,%12,%13};\n"
        : "=f"(d[0]), "=f"(d[1]), "=f"(d[2]), "=f"(d[3])
        : "r"(a[0]), "r"(a[1]), "r"(a[2]), "r"(a[3]),
          "r"(b2[0]), "r"(b2[1]),
          "f"(c[0]), "f"(c[1]), "f"(c[2]), "f"(c[3]));
}
__device__ __forceinline__ unsigned packh2(float lo, float hi) {
    __half2 h = __floats2half2_rn(lo, hi);   // .x = lo bits [15:0]
    return *(unsigned*)&h;
}

// ---------------------------------------------------------------------------
// Kernel 1: fused Q/K/V projection (tf32 raw-mma, unchanged mainloop).
// Epilogue: fp16 outputs; Q pre-scaled by 0.125; V written transposed.
// ---------------------------------------------------------------------------
__global__ void __launch_bounds__(256, 2) proj_kernel(
    const float* __restrict__ x,
    const float* __restrict__ Wq, const float* __restrict__ bq,
    const float* __restrict__ Wk, const float* __restrict__ bk,
    const float* __restrict__ Wv, const float* __restrict__ bv)
{
    extern __shared__ float sm[];          // [2][128][LD]

    const int tid  = threadIdx.x;
    const int warp = tid >> 5;
    const int lane = tid & 31;
    const int g    = lane >> 2;
    const int tig  = lane & 3;
    const size_t row0 = (size_t)blockIdx.x * 128;

    const float* Ws[3] = {Wq, Wk, Wv};

    float cacc[24][4];
#pragma unroll
    for (int j = 0; j < 24; j++)
#pragma unroll
        for (int i = 0; i < 4; i++) cacc[j][i] = 0.0f;

#pragma unroll
    for (int i = 0; i < 8; i++) {
        int idx = tid + i * 256;
        int row = idx >> 4, c4 = idx & 15;
        cp_async16(sm + row * LD + c4 * 4, x + (row0 + row) * DD + c4 * 4);
    }
    cp_async_commit();

    for (int kc = 0; kc < DD / 64; kc++) {
        const int cur = kc & 1;
        const int nxt = cur ^ 1;

        asm volatile("cp.async.wait_group 0;\n");
        __syncthreads();

        if (kc < DD / 64 - 1) {
#pragma unroll
            for (int i = 0; i < 8; i++) {
                int idx = tid + i * 256;
                int row = idx >> 4, c4 = idx & 15;
                cp_async16(sm + nxt * 128 * LD + row * LD + c4 * 4,
                           x + (row0 + row) * DD + (kc + 1) * 64 + c4 * 4);
            }
            cp_async_commit();
        }

        const float* xs = sm + cur * 128 * LD + warp * 16 * LD;
#pragma unroll
        for (int ks = 0; ks < 8; ks++) {
            unsigned a[4];
            a[0] = __float_as_uint(rtf32(xs[(size_t)g * LD + ks * 8 + tig]));
            a[1] = __float_as_uint(rtf32(xs[(size_t)(g + 8) * LD + ks * 8 + tig]));
            a[2] = __float_as_uint(rtf32(xs[(size_t)g * LD + ks * 8 + tig + 4]));
            a[3] = __float_as_uint(rtf32(xs[(size_t)(g + 8) * LD + ks * 8 + tig + 4]));
#pragma unroll
            for (int j = 0; j < 24; j++) {
                const float* wp = Ws[j >> 3] +
                    (size_t)(kc * 64 + ks * 8 + tig) * HH + (j & 7) * 8 + g;
                unsigned b2[2];
                b2[0] = __float_as_uint(wp[0]);
                b2[1] = __float_as_uint(wp[4 * HH]);
                mma16n8k8(cacc[j], a, b2, cacc[j]);
            }
        }
    }

    // epilogue: fp16 outputs
    const size_t rg  = row0 + warp * 16 + g;
    const size_t rg8 = rg + 8;
#pragma unroll
    for (int j = 0; j < 24; j++) {
        int mm = j >> 3;
        int col = (j & 7) * 8 + 2 * tig;
        if (mm == 0) {            // Q: scale folded
            float b0 = bq[col], b1 = bq[col + 1];
            __half2 v0 = __floats2half2_rn(0.125f * (cacc[j][0] + b0), 0.125f * (cacc[j][1] + b1));
            __half2 v8 = __floats2half2_rn(0.125f * (cacc[j][2] + b0), 0.125f * (cacc[j][3] + b1));
            *(__half2*)(g_q + rg * HH + col)  = v0;
            *(__half2*)(g_q + rg8 * HH + col) = v8;
        } else if (mm == 1) {     // K
            float b0 = bk[col], b1 = bk[col + 1];
            __half2 v0 = __floats2half2_rn(cacc[j][0] + b0, cacc[j][1] + b1);
            __half2 v8 = __floats2half2_rn(cacc[j][2] + b0, cacc[j][3] + b1);
            *(__half2*)(g_k + rg * HH + col)  = v0;
            *(__half2*)(g_k + rg8 * HH + col) = v8;
        } else {                  // V: transposed [b][d][n]
            float b0 = bv[col], b1 = bv[col + 1];
            size_t bofs = (rg >> 12) * (size_t)HH * NN;  // batch of this CTA
            size_t n0 = rg & 4095, n8 = rg8 & 4095;
            g_vT[bofs + (size_t)col * NN + n0]       = __float2half_rn(cacc[j][0] + b0);
            g_vT[bofs + (size_t)(col + 1) * NN + n0] = __float2half_rn(cacc[j][1] + b1);
            g_vT[bofs + (size_t)col * NN + n8]       = __float2half_rn(cacc[j][2] + b0);
            g_vT[bofs + (size_t)(col + 1) * NN + n8] = __float2half_rn(cacc[j][3] + b1);
        }
    }
}

// ---------------------------------------------------------------------------
// Kernel 2: flash attention, fp16 m16n8k16, fp32 accumulate, P in registers.
// 8 warps x 16 q-rows = 128 rows/CTA. K tiles [key][d], V tiles [d][key] (from
// g_vT). All fragment loads are single conflict-free 4B LDS.
// ---------------------------------------------------------------------------
__global__ void __launch_bounds__(256, 2) attn_kernel(float* __restrict__ out)
{
    extern __shared__ __half smh[];
    __half* s_k = smh;                  // [2][64][LDH]
    __half* s_v = smh + 2 * TILEH;      // [2][64][LDH]  (V^T: rows=d, cols=keys)

    const int tid  = threadIdx.x;
    const int warp = tid >> 5;
    const int lane = tid & 31;
    const int g    = lane >> 2;
    const int tig  = lane & 3;
    const int b    = blockIdx.y;
    const int q0   = blockIdx.x * 128;

    // ---- persistent Q A-fragments (fp16, scale pre-folded) ----
    const __half* qbase = g_q + (size_t)(b * NN + q0 + warp * 16) * HH;
    unsigned qa[4][4];
#pragma unroll
    for (int kk = 0; kk < 4; kk++) {
        qa[kk][0] = *(const unsigned*)(qbase + (size_t)g * HH + 16 * kk + 2 * tig);
        qa[kk][1] = *(const unsigned*)(qbase + (size_t)(g + 8) * HH + 16 * kk + 2 * tig);
        qa[kk][2] = *(const unsigned*)(qbase + (size_t)g * HH + 16 * kk + 2 * tig + 8);
        qa[kk][3] = *(const unsigned*)(qbase + (size_t)(g + 8) * HH + 16 * kk + 2 * tig + 8);
    }

    unsigned onesb2[2];
    onesb2[0] = onesb2[1] = (g == 0) ? 0x3C003C00u : 0u;   // half2(1,1) in col 0

    float oacc[8][4];
#pragma unroll
    for (int j = 0; j < 8; j++)
#pragma unroll
        for (int i = 0; i < 4; i++) oacc[j][i] = 0.0f;
    float lacc[4] = {0.f, 0.f, 0.f, 0.f};

    // ---- prologue: K/V block 0 (each tile: 64 rows x 128B; 512 chunks/tile) ----
    const __half* gk  = g_k + (size_t)b * NN * HH;
    const __half* gvT = g_vT + (size_t)b * HH * NN;
#pragma unroll
    for (int u = 0; u < 2; u++) {
        int id = tid + u * 256;
        int row = id >> 3, c16 = id & 7;
        cp_async16(s_k + row * LDH + c16 * 8, gk + (size_t)row * HH + c16 * 8);
        cp_async16(s_v + row * LDH + c16 * 8, gvT + (size_t)row * NN + c16 * 8);
    }
    cp_async_commit();

    for (int kb = 0; kb < NN / 64; kb++) {
        const int cur = kb & 1;
        const int nxt = cur ^ 1;

        asm volatile("cp.async.wait_group 0;\n");
        __syncthreads();

        if (kb < NN / 64 - 1) {
            const int k0n = (kb + 1) * 64;
#pragma unroll
            for (int u = 0; u < 2; u++) {
                int id = tid + u * 256;
                int row = id >> 3, c16 = id & 7;
                cp_async16(s_k + nxt * TILEH + row * LDH + c16 * 8,
                           gk + (size_t)(k0n + row) * HH + c16 * 8);
                cp_async16(s_v + nxt * TILEH + row * LDH + c16 * 8,
                           gvT + (size_t)row * NN + k0n + c16 * 8);
            }
            cp_async_commit();
        }

        const __half* kbuf = s_k + cur * TILEH;
        const __half* vbuf = s_v + cur * TILEH;

#pragma unroll
        for (int h = 0; h < 2; h++) {          // 32 keys per half
            const int kc0 = h * 32;

            // ---- S = Q @ K^T : 4 n-tiles (8 keys), contraction 4 x k16 ----
            float sacc[4][4];
#pragma unroll
            for (int c = 0; c < 4; c++)
#pragma unroll
                for (int i = 0; i < 4; i++) sacc[c][i] = 0.0f;

#pragma unroll
            for (int kk = 0; kk < 4; kk++) {
#pragma unroll
                for (int c = 0; c < 4; c++) {
                    const __half* kp = kbuf + (size_t)(kc0 + c * 8 + g) * LDH + 16 * kk;
                    unsigned kb2[2];
                    kb2[0] = *(const unsigned*)(kp + 2 * tig);
                    kb2[1] = *(const unsigned*)(kp + 2 * tig + 8);
                    mmaf16(sacc[c], qa[kk], kb2, sacc[c]);
                }
            }

            // ---- P = exp(S) packed to fp16 A-fragments (2 frags of k16) ----
            unsigned paf[2][4];
#pragma unroll
            for (int cp = 0; cp < 2; cp++) {
                float* s0 = sacc[2 * cp];       // keys [16cp, 16cp+8)
                float* s1 = sacc[2 * cp + 1];   // keys [16cp+8, 16cp+16)
                paf[cp][0] = packh2(__expf(s0[0]), __expf(s0[1]));
                paf[cp][1] = packh2(__expf(s0[2]), __expf(s0[3]));
                paf[cp][2] = packh2(__expf(s1[0]), __expf(s1[1]));
                paf[cp][3] = packh2(__expf(s1[2]), __expf(s1[3]));
            }

            // ---- l += P @ ones ----
#pragma unroll
            for (int cp = 0; cp < 2; cp++)
                mmaf16(lacc, paf[cp], onesb2, lacc);

            // ---- O += P @ V  (V^T tile: row = d, col = key) ----
#pragma unroll
            for (int j = 0; j < 8; j++) {
#pragma unroll
                for (int cp = 0; cp < 2; cp++) {
                    const __half* vp = vbuf + (size_t)(j * 8 + g) * LDH + kc0 + 16 * cp;
                    unsigned vb2[2];
                    vb2[0] = *(const unsigned*)(vp + 2 * tig);
                    vb2[1] = *(const unsigned*)(vp + 2 * tig + 8);
                    mmaf16(oacc[j], paf[cp], vb2, oacc[j]);
                }
            }
        }
    }

    // ---- epilogue: l in col 0 (tig==0 threads); broadcast, divide, store ----
    float lg  = __shfl_sync(0xffffffffu, lacc[0], lane & ~3);
    float lg8 = __shfl_sync(0xffffffffu, lacc[2], lane & ~3);
    float inv0 = 1.0f / lg;
    float inv8 = 1.0f / lg8;

    float* orow0 = out + (size_t)(b * NN + q0 + warp * 16 + g) * HH;
    float* orow8 = out + (size_t)(b * NN + q0 + warp * 16 + g + 8) * HH;
#pragma unroll
    for (int j = 0; j < 8; j++) {
        float2 v0 = make_float2(oacc[j][0] * inv0, oacc[j][1] * inv0);
        float2 v8 = make_float2(oacc[j][2] * inv8, oacc[j][3] * inv8);
        *(float2*)(orow0 + j * 8 + 2 * tig) = v0;
        *(float2*)(orow8 + j * 8 + 2 * tig) = v8;
    }
}

// ---------------------------------------------------------------------------
extern "C" void kernel_launch(void* const* d_in, const int* in_sizes, int n_in,
                              void* d_out, int out_size)
{
    const float* x  = (const float*)d_in[0];
    const float* Wq = (const float*)d_in[1];
    const float* bq = (const float*)d_in[2];
    const float* Wk = (const float*)d_in[3];
    const float* bk = (const float*)d_in[4];
    const float* Wv = (const float*)d_in[5];
    const float* bv = (const float*)d_in[6];
    float* out = (float*)d_out;

    const int smem_proj = (2 * 128 * LD) * (int)sizeof(float);   // 69632
    const int smem_attn = 4 * TILEH * (int)sizeof(__half);       // 36864

    (void)cudaFuncSetAttribute(proj_kernel, cudaFuncAttributeMaxDynamicSharedMemorySize, smem_proj);
    (void)cudaFuncSetAttribute(attn_kernel, cudaFuncAttributeMaxDynamicSharedMemorySize, smem_attn);

    proj_kernel<<<(BB * NN) / 128, 256, smem_proj>>>(x, Wq, bq, Wk, bk, Wv, bv);
    attn_kernel<<<dim3(NN / 128, BB), 256, smem_attn>>>(out);
}

// round 10
// speedup vs baseline: 7.8777x; 1.6394x over previous
#include <cuda_runtime.h>
#include <cuda_fp16.h>
#include <cstdint>
#include <mma.h>

// Problem constants
#define BB 8
#define NN 4096
#define DD 768
#define HH 64

// attn smem leading dim (halves): 72 -> bank = 4g+tig, conflict-free
#define LDH 72
#define TILEH (64 * LDH)

// proj smem tiles (halves)
#define PLDH 72
#define XBUF (64 * PLDH)          // one x tile: 64 rows x 64 k
#define WBUF (3 * 64 * PLDH)      // one W chunk: 3 mats x 64 n x 64 k

// Device scratch: fp16 projections. Q has 1/8 scale pre-folded. V stored transposed [b][d][n].
__device__ __half g_q[BB * NN * HH];
__device__ __half g_k[BB * NN * HH];
__device__ __half g_vT[BB * HH * NN];
// fp16 transposed weights [mm][n][k]
__device__ __half g_whT[3 * HH * DD];

// ---------------------------------------------------------------------------
// helpers
// ---------------------------------------------------------------------------
__device__ __forceinline__ void cp_async16(void* smem_dst, const void* gmem_src) {
    unsigned s = (unsigned)__cvta_generic_to_shared(smem_dst);
    asm volatile("cp.async.cg.shared.global [%0], [%1], 16;\n" :: "r"(s), "l"(gmem_src));
}
__device__ __forceinline__ void cp_async_commit() {
    asm volatile("cp.async.commit_group;\n");
}
// f16 m16n8k16, f32 accumulate
__device__ __forceinline__ void mmaf16(float* d, const unsigned* a, const unsigned* b2,
                                       const float* c) {
    asm volatile(
        "mma.sync.aligned.m16n8k16.row.col.f32.f16.f16.f32 "
        "{%0,%1,%2,%3}, {%4,%5,%6,%7}, {%8,%9}, {%10,%11,%12,%13};\n"
        : "=f"(d[0]), "=f"(d[1]), "=f"(d[2]), "=f"(d[3])
        : "r"(a[0]), "r"(a[1]), "r"(a[2]), "r"(a[3]),
          "r"(b2[0]), "r"(b2[1]),
          "f"(c[0]), "f"(c[1]), "f"(c[2]), "f"(c[3]));
}
__device__ __forceinline__ unsigned packh2(float lo, float hi) {
    __half2 h = __floats2half2_rn(lo, hi);
    return *(unsigned*)&h;
}

// ---------------------------------------------------------------------------
// Kernel 0: W -> fp16 transposed [mm][n][k]. 147456 elems, trivial.
// ---------------------------------------------------------------------------
__global__ void wconv_kernel(const float* __restrict__ Wq,
                             const float* __restrict__ Wk,
                             const float* __restrict__ Wv)
{
    int id = blockIdx.x * 256 + threadIdx.x;          // 0 .. 147455
    int k = id % DD;
    int rem = id / DD;
    int n = rem & 63;
    int mm = rem >> 6;
    const float* W = (mm == 0) ? Wq : (mm == 1) ? Wk : Wv;
    g_whT[(size_t)mm * HH * DD + (size_t)n * DD + k] = __float2half_rn(W[(size_t)k * HH + n]);
}

// ---------------------------------------------------------------------------
// Kernel 1: fused Q/K/V projection, fp16 m16n8k16.
// 512 CTAs x 64 rows, 8 warps: warp (rg = warp&3, ch = warp>>2) owns
// 16 rows x 96 cols = 12 C-frags. x: LDG float4 -> pack fp16 -> STS
// (double-buffered, prefetch distance 2). W: cp.async fp16 chunks from g_whT.
// ---------------------------------------------------------------------------
__global__ void __launch_bounds__(256, 2) proj_kernel(
    const float* __restrict__ x,
    const float* __restrict__ bq, const float* __restrict__ bk,
    const float* __restrict__ bv)
{
    extern __shared__ __half smh[];
    __half* xsm = smh;                 // [2][64][PLDH]
    __half* wsm = smh + 2 * XBUF;      // [2][3][64][PLDH]

    const int tid  = threadIdx.x;
    const int warp = tid >> 5;
    const int lane = tid & 31;
    const int g    = lane >> 2;
    const int tig  = lane & 3;
    const int rg   = warp & 3;         // row group (16 rows)
    const int ch   = warp >> 2;        // column half (96 cols)
    const size_t row0 = (size_t)blockIdx.x * 64;

    const int lrow = tid >> 4;         // x LDG mapping: 4 float4 / thread / chunk
    const int lc4  = tid & 15;

    float cacc[12][4];
#pragma unroll
    for (int j = 0; j < 12; j++)
#pragma unroll
        for (int i = 0; i < 4; i++) cacc[j][i] = 0.0f;

    uint2 ph[4];

    // ---- x LDG + pack for chunk kc ----
#define LDX(kc)                                                                     \
    do {                                                                            \
        _Pragma("unroll")                                                           \
        for (int i = 0; i < 4; i++) {                                               \
            int row = lrow + i * 16;                                                \
            float4 v = *(const float4*)(x + (row0 + row) * DD + (kc) * 64 + lc4 * 4); \
            ph[i].x = packh2(v.x, v.y);                                             \
            ph[i].y = packh2(v.z, v.w);                                             \
        }                                                                           \
    } while (0)

#define STX(buf)                                                                    \
    do {                                                                            \
        _Pragma("unroll")                                                           \
        for (int i = 0; i < 4; i++) {                                               \
            int row = lrow + i * 16;                                                \
            *(uint2*)(xsm + (buf) * XBUF + row * PLDH + lc4 * 4) = ph[i];           \
        }                                                                           \
    } while (0)

#define LDW(kc, buf)                                                                \
    do {                                                                            \
        _Pragma("unroll")                                                           \
        for (int u = 0; u < 6; u++) {                                               \
            int t = tid + u * 256;                                                  \
            int mm = t >> 9, rem = t & 511, n = rem >> 3, c16 = rem & 7;            \
            cp_async16(wsm + (buf) * WBUF + mm * (64 * PLDH) + n * PLDH + c16 * 8,  \
                       g_whT + (size_t)mm * HH * DD + (size_t)n * DD + (kc) * 64 + c16 * 8); \
        }                                                                           \
        cp_async_commit();                                                          \
    } while (0)

    // prologue
    LDX(0);
    LDW(0, 0);
    STX(0);
    LDX(1);

    for (int kc = 0; kc < DD / 64; kc++) {
        const int cur = kc & 1;
        const int nxt = cur ^ 1;

        asm volatile("cp.async.wait_group 0;\n");
        __syncthreads();

        if (kc < DD / 64 - 1) {
            LDW(kc + 1, nxt);
            STX(nxt);                  // ph holds chunk kc+1
        }

        // ---- mma on current buffers ----
        const __half* xs = xsm + cur * XBUF + rg * 16 * PLDH;
        unsigned a[4][4];
#pragma unroll
        for (int kk = 0; kk < 4; kk++) {
            a[kk][0] = *(const unsigned*)(xs + (size_t)g * PLDH + 16 * kk + 2 * tig);
            a[kk][1] = *(const unsigned*)(xs + (size_t)(g + 8) * PLDH + 16 * kk + 2 * tig);
            a[kk][2] = *(const unsigned*)(xs + (size_t)g * PLDH + 16 * kk + 2 * tig + 8);
            a[kk][3] = *(const unsigned*)(xs + (size_t)(g + 8) * PLDH + 16 * kk + 2 * tig + 8);
        }
#pragma unroll
        for (int j = 0; j < 12; j++) {
            int jj = ch * 12 + j;
            int mm = jj >> 3, nt = jj & 7;
            const __half* wt = wsm + cur * WBUF + mm * (64 * PLDH) + (nt * 8 + g) * PLDH;
#pragma unroll
            for (int kk = 0; kk < 4; kk++) {
                unsigned b2[2];
                b2[0] = *(const unsigned*)(wt + 16 * kk + 2 * tig);
                b2[1] = *(const unsigned*)(wt + 16 * kk + 2 * tig + 8);
                mmaf16(cacc[j], a[kk], b2, cacc[j]);
            }
        }

        if (kc < DD / 64 - 2) LDX(kc + 2);
    }

    // ---- epilogue: fp16 outputs; Q pre-scaled; V transposed ----
    const size_t rgg  = row0 + rg * 16 + g;
    const size_t rgg8 = rgg + 8;
#pragma unroll
    for (int j = 0; j < 12; j++) {
        int jj = ch * 12 + j;
        int mm = jj >> 3;
        int col = (jj & 7) * 8 + 2 * tig;
        if (mm == 0) {
            float b0 = bq[col], b1 = bq[col + 1];
            __half2 v0 = __floats2half2_rn(0.125f * (cacc[j][0] + b0), 0.125f * (cacc[j][1] + b1));
            __half2 v8 = __floats2half2_rn(0.125f * (cacc[j][2] + b0), 0.125f * (cacc[j][3] + b1));
            *(__half2*)(g_q + rgg * HH + col)  = v0;
            *(__half2*)(g_q + rgg8 * HH + col) = v8;
        } else if (mm == 1) {
            float b0 = bk[col], b1 = bk[col + 1];
            __half2 v0 = __floats2half2_rn(cacc[j][0] + b0, cacc[j][1] + b1);
            __half2 v8 = __floats2half2_rn(cacc[j][2] + b0, cacc[j][3] + b1);
            *(__half2*)(g_k + rgg * HH + col)  = v0;
            *(__half2*)(g_k + rgg8 * HH + col) = v8;
        } else {
            float b0 = bv[col], b1 = bv[col + 1];
            size_t bofs = (rgg >> 12) * (size_t)HH * NN;
            size_t n0 = rgg & 4095, n8 = rgg8 & 4095;
            g_vT[bofs + (size_t)col * NN + n0]       = __float2half_rn(cacc[j][0] + b0);
            g_vT[bofs + (size_t)(col + 1) * NN + n0] = __float2half_rn(cacc[j][1] + b1);
            g_vT[bofs + (size_t)col * NN + n8]       = __float2half_rn(cacc[j][2] + b0);
            g_vT[bofs + (size_t)(col + 1) * NN + n8] = __float2half_rn(cacc[j][3] + b1);
        }
    }
#undef LDX
#undef STX
#undef LDW
}

// ---------------------------------------------------------------------------
// Kernel 2: flash attention (byte-identical to R9 — 141.9us, rel_err 4.3e-4)
// ---------------------------------------------------------------------------
__global__ void __launch_bounds__(256, 2) attn_kernel(float* __restrict__ out)
{
    extern __shared__ __half smh[];
    __half* s_k = smh;                  // [2][64][LDH]
    __half* s_v = smh + 2 * TILEH;      // [2][64][LDH]  (V^T: rows=d, cols=keys)

    const int tid  = threadIdx.x;
    const int warp = tid >> 5;
    const int lane = tid & 31;
    const int g    = lane >> 2;
    const int tig  = lane & 3;
    const int b    = blockIdx.y;
    const int q0   = blockIdx.x * 128;

    const __half* qbase = g_q + (size_t)(b * NN + q0 + warp * 16) * HH;
    unsigned qa[4][4];
#pragma unroll
    for (int kk = 0; kk < 4; kk++) {
        qa[kk][0] = *(const unsigned*)(qbase + (size_t)g * HH + 16 * kk + 2 * tig);
        qa[kk][1] = *(const unsigned*)(qbase + (size_t)(g + 8) * HH + 16 * kk + 2 * tig);
        qa[kk][2] = *(const unsigned*)(qbase + (size_t)g * HH + 16 * kk + 2 * tig + 8);
        qa[kk][3] = *(const unsigned*)(qbase + (size_t)(g + 8) * HH + 16 * kk + 2 * tig + 8);
    }

    unsigned onesb2[2];
    onesb2[0] = onesb2[1] = (g == 0) ? 0x3C003C00u : 0u;

    float oacc[8][4];
#pragma unroll
    for (int j = 0; j < 8; j++)
#pragma unroll
        for (int i = 0; i < 4; i++) oacc[j][i] = 0.0f;
    float lacc[4] = {0.f, 0.f, 0.f, 0.f};

    const __half* gk  = g_k + (size_t)b * NN * HH;
    const __half* gvT = g_vT + (size_t)b * HH * NN;
#pragma unroll
    for (int u = 0; u < 2; u++) {
        int id = tid + u * 256;
        int row = id >> 3, c16 = id & 7;
        cp_async16(s_k + row * LDH + c16 * 8, gk + (size_t)row * HH + c16 * 8);
        cp_async16(s_v + row * LDH + c16 * 8, gvT + (size_t)row * NN + c16 * 8);
    }
    cp_async_commit();

    for (int kb = 0; kb < NN / 64; kb++) {
        const int cur = kb & 1;
        const int nxt = cur ^ 1;

        asm volatile("cp.async.wait_group 0;\n");
        __syncthreads();

        if (kb < NN / 64 - 1) {
            const int k0n = (kb + 1) * 64;
#pragma unroll
            for (int u = 0; u < 2; u++) {
                int id = tid + u * 256;
                int row = id >> 3, c16 = id & 7;
                cp_async16(s_k + nxt * TILEH + row * LDH + c16 * 8,
                           gk + (size_t)(k0n + row) * HH + c16 * 8);
                cp_async16(s_v + nxt * TILEH + row * LDH + c16 * 8,
                           gvT + (size_t)row * NN + k0n + c16 * 8);
            }
            cp_async_commit();
        }

        const __half* kbuf = s_k + cur * TILEH;
        const __half* vbuf = s_v + cur * TILEH;

#pragma unroll
        for (int h = 0; h < 2; h++) {
            const int kc0 = h * 32;

            float sacc[4][4];
#pragma unroll
            for (int c = 0; c < 4; c++)
#pragma unroll
                for (int i = 0; i < 4; i++) sacc[c][i] = 0.0f;

#pragma unroll
            for (int kk = 0; kk < 4; kk++) {
#pragma unroll
                for (int c = 0; c < 4; c++) {
                    const __half* kp = kbuf + (size_t)(kc0 + c * 8 + g) * LDH + 16 * kk;
                    unsigned kb2[2];
                    kb2[0] = *(const unsigned*)(kp + 2 * tig);
                    kb2[1] = *(const unsigned*)(kp + 2 * tig + 8);
                    mmaf16(sacc[c], qa[kk], kb2, sacc[c]);
                }
            }

            unsigned paf[2][4];
#pragma unroll
            for (int cp = 0; cp < 2; cp++) {
                float* s0 = sacc[2 * cp];
                float* s1 = sacc[2 * cp + 1];
                paf[cp][0] = packh2(__expf(s0[0]), __expf(s0[1]));
                paf[cp][1] = packh2(__expf(s0[2]), __expf(s0[3]));
                paf[cp][2] = packh2(__expf(s1[0]), __expf(s1[1]));
                paf[cp][3] = packh2(__expf(s1[2]), __expf(s1[3]));
            }

#pragma unroll
            for (int cp = 0; cp < 2; cp++)
                mmaf16(lacc, paf[cp], onesb2, lacc);

#pragma unroll
            for (int j = 0; j < 8; j++) {
#pragma unroll
                for (int cp = 0; cp < 2; cp++) {
                    const __half* vp = vbuf + (size_t)(j * 8 + g) * LDH + kc0 + 16 * cp;
                    unsigned vb2[2];
                    vb2[0] = *(const unsigned*)(vp + 2 * tig);
                    vb2[1] = *(const unsigned*)(vp + 2 * tig + 8);
                    mmaf16(oacc[j], paf[cp], vb2, oacc[j]);
                }
            }
        }
    }

    float lg  = __shfl_sync(0xffffffffu, lacc[0], lane & ~3);
    float lg8 = __shfl_sync(0xffffffffu, lacc[2], lane & ~3);
    float inv0 = 1.0f / lg;
    float inv8 = 1.0f / lg8;

    float* orow0 = out + (size_t)(b * NN + q0 + warp * 16 + g) * HH;
    float* orow8 = out + (size_t)(b * NN + q0 + warp * 16 + g + 8) * HH;
#pragma unroll
    for (int j = 0; j < 8; j++) {
        float2 v0 = make_float2(oacc[j][0] * inv0, oacc[j][1] * inv0);
        float2 v8 = make_float2(oacc[j][2] * inv8, oacc[j][3] * inv8);
        *(float2*)(orow0 + j * 8 + 2 * tig) = v0;
        *(float2*)(orow8 + j * 8 + 2 * tig) = v8;
    }
}

// ---------------------------------------------------------------------------
extern "C" void kernel_launch(void* const* d_in, const int* in_sizes, int n_in,
                              void* d_out, int out_size)
{
    const float* x  = (const float*)d_in[0];
    const float* Wq = (const float*)d_in[1];
    const float* bq = (const float*)d_in[2];
    const float* Wk = (const float*)d_in[3];
    const float* bk = (const float*)d_in[4];
    const float* Wv = (const float*)d_in[5];
    const float* bv = (const float*)d_in[6];
    float* out = (float*)d_out;

    const int smem_proj = (2 * XBUF + 2 * WBUF) * (int)sizeof(__half);   // 73728
    const int smem_attn = 4 * TILEH * (int)sizeof(__half);               // 36864

    (void)cudaFuncSetAttribute(proj_kernel, cudaFuncAttributeMaxDynamicSharedMemorySize, smem_proj);
    (void)cudaFuncSetAttribute(attn_kernel, cudaFuncAttributeMaxDynamicSharedMemorySize, smem_attn);

    wconv_kernel<<<(3 * HH * DD) / 256, 256>>>(Wq, Wk, Wv);
    proj_kernel<<<(BB * NN) / 64, 256, smem_proj>>>(x, bq, bk, bv);
    attn_kernel<<<dim3(NN / 128, BB), 256, smem_attn>>>(out);
}

// round 11
// speedup vs baseline: 7.8828x; 1.0006x over previous
#include <cuda_runtime.h>
#include <cuda_fp16.h>
#include <cstdint>
#include <mma.h>

// Problem constants
#define BB 8
#define NN 4096
#define DD 768
#define HH 64

// attn smem leading dim (halves): 72 -> bank = 4g+tig, conflict-free
#define LDH 72
#define TILEH (64 * LDH)

// proj smem tiles (halves)
#define PLDH 72
#define XBUF (64 * PLDH)          // one x tile: 64 rows x 64 k
#define WBUF (3 * 64 * PLDH)      // one W chunk: 3 mats x 64 n x 64 k

// Device scratch: fp16 projections. Q has 1/8 scale pre-folded. V stored transposed [b][d][n].
__device__ __half g_q[BB * NN * HH];
__device__ __half g_k[BB * NN * HH];
__device__ __half g_vT[BB * HH * NN];
// fp16 transposed weights [mm][n][k]
__device__ __half g_whT[3 * HH * DD];

// ---------------------------------------------------------------------------
// helpers
// ---------------------------------------------------------------------------
__device__ __forceinline__ void cp_async16(void* smem_dst, const void* gmem_src) {
    unsigned s = (unsigned)__cvta_generic_to_shared(smem_dst);
    asm volatile("cp.async.cg.shared.global [%0], [%1], 16;\n" :: "r"(s), "l"(gmem_src));
}
__device__ __forceinline__ void cp_async_commit() {
    asm volatile("cp.async.commit_group;\n");
}
// f16 m16n8k16, f32 accumulate
__device__ __forceinline__ void mmaf16(float* d, const unsigned* a, const unsigned* b2,
                                       const float* c) {
    asm volatile(
        "mma.sync.aligned.m16n8k16.row.col.f32.f16.f16.f32 "
        "{%0,%1,%2,%3}, {%4,%5,%6,%7}, {%8,%9}, {%10,%11,%12,%13};\n"
        : "=f"(d[0]), "=f"(d[1]), "=f"(d[2]), "=f"(d[3])
        : "r"(a[0]), "r"(a[1]), "r"(a[2]), "r"(a[3]),
          "r"(b2[0]), "r"(b2[1]),
          "f"(c[0]), "f"(c[1]), "f"(c[2]), "f"(c[3]));
}
__device__ __forceinline__ unsigned packh2(float lo, float hi) {
    __half2 h = __floats2half2_rn(lo, hi);
    return *(unsigned*)&h;
}
// ldmatrix x4: 4 B-fragments (8x8 b16 each) in one instruction
__device__ __forceinline__ void ldsm4(unsigned* r, unsigned saddr) {
    asm volatile("ldmatrix.sync.aligned.m8n8.x4.shared.b16 {%0,%1,%2,%3}, [%4];\n"
                 : "=r"(r[0]), "=r"(r[1]), "=r"(r[2]), "=r"(r[3]) : "r"(saddr));
}

// ---------------------------------------------------------------------------
// Kernel 0: W -> fp16 transposed [mm][n][k]. 147456 elems, trivial.
// ---------------------------------------------------------------------------
__global__ void wconv_kernel(const float* __restrict__ Wq,
                             const float* __restrict__ Wk,
                             const float* __restrict__ Wv)
{
    int id = blockIdx.x * 256 + threadIdx.x;
    int k = id % DD;
    int rem = id / DD;
    int n = rem & 63;
    int mm = rem >> 6;
    const float* W = (mm == 0) ? Wq : (mm == 1) ? Wk : Wv;
    g_whT[(size_t)mm * HH * DD + (size_t)n * DD + k] = __float2half_rn(W[(size_t)k * HH + n]);
}

// ---------------------------------------------------------------------------
// Kernel 1: fused Q/K/V projection, fp16 m16n8k16 (byte-identical to R10).
// ---------------------------------------------------------------------------
__global__ void __launch_bounds__(256, 2) proj_kernel(
    const float* __restrict__ x,
    const float* __restrict__ bq, const float* __restrict__ bk,
    const float* __restrict__ bv)
{
    extern __shared__ __half smh[];
    __half* xsm = smh;                 // [2][64][PLDH]
    __half* wsm = smh + 2 * XBUF;      // [2][3][64][PLDH]

    const int tid  = threadIdx.x;
    const int warp = tid >> 5;
    const int lane = tid & 31;
    const int g    = lane >> 2;
    const int tig  = lane & 3;
    const int rg   = warp & 3;
    const int ch   = warp >> 2;
    const size_t row0 = (size_t)blockIdx.x * 64;

    const int lrow = tid >> 4;
    const int lc4  = tid & 15;

    float cacc[12][4];
#pragma unroll
    for (int j = 0; j < 12; j++)
#pragma unroll
        for (int i = 0; i < 4; i++) cacc[j][i] = 0.0f;

    uint2 ph[4];

#define LDX(kc)                                                                     \
    do {                                                                            \
        _Pragma("unroll")                                                           \
        for (int i = 0; i < 4; i++) {                                               \
            int row = lrow + i * 16;                                                \
            float4 v = *(const float4*)(x + (row0 + row) * DD + (kc) * 64 + lc4 * 4); \
            ph[i].x = packh2(v.x, v.y);                                             \
            ph[i].y = packh2(v.z, v.w);                                             \
        }                                                                           \
    } while (0)

#define STX(buf)                                                                    \
    do {                                                                            \
        _Pragma("unroll")                                                           \
        for (int i = 0; i < 4; i++) {                                               \
            int row = lrow + i * 16;                                                \
            *(uint2*)(xsm + (buf) * XBUF + row * PLDH + lc4 * 4) = ph[i];           \
        }                                                                           \
    } while (0)

#define LDW(kc, buf)                                                                \
    do {                                                                            \
        _Pragma("unroll")                                                           \
        for (int u = 0; u < 6; u++) {                                               \
            int t = tid + u * 256;                                                  \
            int mm = t >> 9, rem = t & 511, n = rem >> 3, c16 = rem & 7;            \
            cp_async16(wsm + (buf) * WBUF + mm * (64 * PLDH) + n * PLDH + c16 * 8,  \
                       g_whT + (size_t)mm * HH * DD + (size_t)n * DD + (kc) * 64 + c16 * 8); \
        }                                                                           \
        cp_async_commit();                                                          \
    } while (0)

    LDX(0);
    LDW(0, 0);
    STX(0);
    LDX(1);

    for (int kc = 0; kc < DD / 64; kc++) {
        const int cur = kc & 1;
        const int nxt = cur ^ 1;

        asm volatile("cp.async.wait_group 0;\n");
        __syncthreads();

        if (kc < DD / 64 - 1) {
            LDW(kc + 1, nxt);
            STX(nxt);
        }

        const __half* xs = xsm + cur * XBUF + rg * 16 * PLDH;
        unsigned a[4][4];
#pragma unroll
        for (int kk = 0; kk < 4; kk++) {
            a[kk][0] = *(const unsigned*)(xs + (size_t)g * PLDH + 16 * kk + 2 * tig);
            a[kk][1] = *(const unsigned*)(xs + (size_t)(g + 8) * PLDH + 16 * kk + 2 * tig);
            a[kk][2] = *(const unsigned*)(xs + (size_t)g * PLDH + 16 * kk + 2 * tig + 8);
            a[kk][3] = *(const unsigned*)(xs + (size_t)(g + 8) * PLDH + 16 * kk + 2 * tig + 8);
        }
#pragma unroll
        for (int j = 0; j < 12; j++) {
            int jj = ch * 12 + j;
            int mm = jj >> 3, nt = jj & 7;
            const __half* wt = wsm + cur * WBUF + mm * (64 * PLDH) + (nt * 8 + g) * PLDH;
#pragma unroll
            for (int kk = 0; kk < 4; kk++) {
                unsigned b2[2];
                b2[0] = *(const unsigned*)(wt + 16 * kk + 2 * tig);
                b2[1] = *(const unsigned*)(wt + 16 * kk + 2 * tig + 8);
                mmaf16(cacc[j], a[kk], b2, cacc[j]);
            }
        }

        if (kc < DD / 64 - 2) LDX(kc + 2);
    }

    const size_t rgg  = row0 + rg * 16 + g;
    const size_t rgg8 = rgg + 8;
#pragma unroll
    for (int j = 0; j < 12; j++) {
        int jj = ch * 12 + j;
        int mm = jj >> 3;
        int col = (jj & 7) * 8 + 2 * tig;
        if (mm == 0) {
            float b0 = bq[col], b1 = bq[col + 1];
            __half2 v0 = __floats2half2_rn(0.125f * (cacc[j][0] + b0), 0.125f * (cacc[j][1] + b1));
            __half2 v8 = __floats2half2_rn(0.125f * (cacc[j][2] + b0), 0.125f * (cacc[j][3] + b1));
            *(__half2*)(g_q + rgg * HH + col)  = v0;
            *(__half2*)(g_q + rgg8 * HH + col) = v8;
        } else if (mm == 1) {
            float b0 = bk[col], b1 = bk[col + 1];
            __half2 v0 = __floats2half2_rn(cacc[j][0] + b0, cacc[j][1] + b1);
            __half2 v8 = __floats2half2_rn(cacc[j][2] + b0, cacc[j][3] + b1);
            *(__half2*)(g_k + rgg * HH + col)  = v0;
            *(__half2*)(g_k + rgg8 * HH + col) = v8;
        } else {
            float b0 = bv[col], b1 = bv[col + 1];
            size_t bofs = (rgg >> 12) * (size_t)HH * NN;
            size_t n0 = rgg & 4095, n8 = rgg8 & 4095;
            g_vT[bofs + (size_t)col * NN + n0]       = __float2half_rn(cacc[j][0] + b0);
            g_vT[bofs + (size_t)(col + 1) * NN + n0] = __float2half_rn(cacc[j][1] + b1);
            g_vT[bofs + (size_t)col * NN + n8]       = __float2half_rn(cacc[j][2] + b0);
            g_vT[bofs + (size_t)(col + 1) * NN + n8] = __float2half_rn(cacc[j][3] + b1);
        }
    }
#undef LDX
#undef STX
#undef LDW
}

// ---------------------------------------------------------------------------
// Kernel 2: flash attention, fp16 mma + ldmatrix.x4 for all K/V fragments.
// Same math/layout as R9/R10 (bit-identical fragment contents), 4x fewer
// LSU instructions.
// ---------------------------------------------------------------------------
__global__ void __launch_bounds__(256, 2) attn_kernel(float* __restrict__ out)
{
    extern __shared__ __half smh[];
    __half* s_k = smh;                  // [2][64][LDH]
    __half* s_v = smh + 2 * TILEH;      // [2][64][LDH]  (V^T: rows=d, cols=keys)

    const int tid  = threadIdx.x;
    const int warp = tid >> 5;
    const int lane = tid & 31;
    const int g    = lane >> 2;
    const int tig  = lane & 3;
    const int mat  = lane >> 3;         // ldmatrix matrix id 0..3
    const int r8   = lane & 7;          // ldmatrix row within matrix
    const int b    = blockIdx.y;
    const int q0   = blockIdx.x * 128;

    const unsigned sk_u = (unsigned)__cvta_generic_to_shared(s_k);
    const unsigned sv_u = (unsigned)__cvta_generic_to_shared(s_v);

    // ---- persistent Q A-fragments (fp16, scale pre-folded) ----
    const __half* qbase = g_q + (size_t)(b * NN + q0 + warp * 16) * HH;
    unsigned qa[4][4];
#pragma unroll
    for (int kk = 0; kk < 4; kk++) {
        qa[kk][0] = *(const unsigned*)(qbase + (size_t)g * HH + 16 * kk + 2 * tig);
        qa[kk][1] = *(const unsigned*)(qbase + (size_t)(g + 8) * HH + 16 * kk + 2 * tig);
        qa[kk][2] = *(const unsigned*)(qbase + (size_t)g * HH + 16 * kk + 2 * tig + 8);
        qa[kk][3] = *(const unsigned*)(qbase + (size_t)(g + 8) * HH + 16 * kk + 2 * tig + 8);
    }

    unsigned onesb2[2];
    onesb2[0] = onesb2[1] = (g == 0) ? 0x3C003C00u : 0u;

    float oacc[8][4];
#pragma unroll
    for (int j = 0; j < 8; j++)
#pragma unroll
        for (int i = 0; i < 4; i++) oacc[j][i] = 0.0f;
    float lacc[4] = {0.f, 0.f, 0.f, 0.f};

    const __half* gk  = g_k + (size_t)b * NN * HH;
    const __half* gvT = g_vT + (size_t)b * HH * NN;
#pragma unroll
    for (int u = 0; u < 2; u++) {
        int id = tid + u * 256;
        int row = id >> 3, c16 = id & 7;
        cp_async16(s_k + row * LDH + c16 * 8, gk + (size_t)row * HH + c16 * 8);
        cp_async16(s_v + row * LDH + c16 * 8, gvT + (size_t)row * NN + c16 * 8);
    }
    cp_async_commit();

    for (int kb = 0; kb < NN / 64; kb++) {
        const int cur = kb & 1;
        const int nxt = cur ^ 1;

        asm volatile("cp.async.wait_group 0;\n");
        __syncthreads();

        if (kb < NN / 64 - 1) {
            const int k0n = (kb + 1) * 64;
#pragma unroll
            for (int u = 0; u < 2; u++) {
                int id = tid + u * 256;
                int row = id >> 3, c16 = id & 7;
                cp_async16(s_k + nxt * TILEH + row * LDH + c16 * 8,
                           gk + (size_t)(k0n + row) * HH + c16 * 8);
                cp_async16(s_v + nxt * TILEH + row * LDH + c16 * 8,
                           gvT + (size_t)row * NN + k0n + c16 * 8);
            }
            cp_async_commit();
        }

        const unsigned kbase = sk_u + cur * TILEH * 2;
        const unsigned vbase = sv_u + cur * TILEH * 2;

#pragma unroll
        for (int h = 0; h < 2; h++) {
            const int kc0 = h * 32;

            // ---- S = Q @ K^T via ldmatrix ----
            // x4 #1: mats = {c0 k-lo, c0 k-hi, c1 k-lo, c1 k-hi}; x4 #2: c2, c3
            const unsigned ka = kbase +
                ((unsigned)((kc0 + ((mat >> 1) << 3) + r8) * LDH + ((mat & 1) << 3)) << 1);
            float sacc[4][4];
#pragma unroll
            for (int c = 0; c < 4; c++)
#pragma unroll
                for (int i = 0; i < 4; i++) sacc[c][i] = 0.0f;

#pragma unroll
            for (int kk = 0; kk < 4; kk++) {
                unsigned kf[8];
                ldsm4(kf,     ka + kk * 32);
                ldsm4(kf + 4, ka + 16 * LDH * 2 + kk * 32);
                mmaf16(sacc[0], qa[kk], kf + 0, sacc[0]);
                mmaf16(sacc[1], qa[kk], kf + 2, sacc[1]);
                mmaf16(sacc[2], qa[kk], kf + 4, sacc[2]);
                mmaf16(sacc[3], qa[kk], kf + 6, sacc[3]);
            }

            // ---- P = exp(S) packed to fp16 A-fragments ----
            unsigned paf[2][4];
#pragma unroll
            for (int cp = 0; cp < 2; cp++) {
                float* s0 = sacc[2 * cp];
                float* s1 = sacc[2 * cp + 1];
                paf[cp][0] = packh2(__expf(s0[0]), __expf(s0[1]));
                paf[cp][1] = packh2(__expf(s0[2]), __expf(s0[3]));
                paf[cp][2] = packh2(__expf(s1[0]), __expf(s1[1]));
                paf[cp][3] = packh2(__expf(s1[2]), __expf(s1[3]));
            }

            // ---- l += P @ ones ----
#pragma unroll
            for (int cp = 0; cp < 2; cp++)
                mmaf16(lacc, paf[cp], onesb2, lacc);

            // ---- O += P @ V via ldmatrix: per j one x4 = {cp0-lo, cp0-hi, cp1-lo, cp1-hi} ----
            const unsigned va = vbase +
                ((unsigned)(r8 * LDH + kc0 + mat * 8) << 1);
#pragma unroll
            for (int j = 0; j < 8; j++) {
                unsigned vf[4];
                ldsm4(vf, va + j * 8 * LDH * 2);
                mmaf16(oacc[j], paf[0], vf + 0, oacc[j]);
                mmaf16(oacc[j], paf[1], vf + 2, oacc[j]);
            }
        }
    }

    float lg  = __shfl_sync(0xffffffffu, lacc[0], lane & ~3);
    float lg8 = __shfl_sync(0xffffffffu, lacc[2], lane & ~3);
    float inv0 = 1.0f / lg;
    float inv8 = 1.0f / lg8;

    float* orow0 = out + (size_t)(b * NN + q0 + warp * 16 + g) * HH;
    float* orow8 = out + (size_t)(b * NN + q0 + warp * 16 + g + 8) * HH;
#pragma unroll
    for (int j = 0; j < 8; j++) {
        float2 v0 = make_float2(oacc[j][0] * inv0, oacc[j][1] * inv0);
        float2 v8 = make_float2(oacc[j][2] * inv8, oacc[j][3] * inv8);
        *(float2*)(orow0 + j * 8 + 2 * tig) = v0;
        *(float2*)(orow8 + j * 8 + 2 * tig) = v8;
    }
}

// ---------------------------------------------------------------------------
extern "C" void kernel_launch(void* const* d_in, const int* in_sizes, int n_in,
                              void* d_out, int out_size)
{
    const float* x  = (const float*)d_in[0];
    const float* Wq = (const float*)d_in[1];
    const float* bq = (const float*)d_in[2];
    const float* Wk = (const float*)d_in[3];
    const float* bk = (const float*)d_in[4];
    const float* Wv = (const float*)d_in[5];
    const float* bv = (const float*)d_in[6];
    float* out = (float*)d_out;

    const int smem_proj = (2 * XBUF + 2 * WBUF) * (int)sizeof(__half);   // 73728
    const int smem_attn = 4 * TILEH * (int)sizeof(__half);               // 36864

    (void)cudaFuncSetAttribute(proj_kernel, cudaFuncAttributeMaxDynamicSharedMemorySize, smem_proj);
    (void)cudaFuncSetAttribute(attn_kernel, cudaFuncAttributeMaxDynamicSharedMemorySize, smem_attn);

    wconv_kernel<<<(3 * HH * DD) / 256, 256>>>(Wq, Wk, Wv);
    proj_kernel<<<(BB * NN) / 64, 256, smem_proj>>>(x, bq, bk, bv);
    attn_kernel<<<dim3(NN / 128, BB), 256, smem_attn>>>(out);
}

// round 12
// speedup vs baseline: 8.0423x; 1.0202x over previous
#include <cuda_runtime.h>
#include <cuda_fp16.h>
#include <cstdint>
#include <mma.h>

// Problem constants
#define BB 8
#define NN 4096
#define DD 768
#define HH 64

// attn smem leading dim (halves): 72 -> bank = 4g+tig, conflict-free
#define LDH 72
#define TILEH (64 * LDH)

// proj smem tiles (halves)
#define PLDH 72
#define XBUF (64 * PLDH)          // one x tile: 64 rows x 64 k
#define WBUF (3 * 64 * PLDH)      // one W chunk: 3 mats x 64 n x 64 k

// Q prescale: 1/sqrt(64) * log2(e), folded so attn can use ex2 directly
#define QSCALE 0.18033688f

// Device scratch: fp16 projections. Q has QSCALE pre-folded. V stored transposed [b][d][n].
__device__ __half g_q[BB * NN * HH];
__device__ __half g_k[BB * NN * HH];
__device__ __half g_vT[BB * HH * NN];
// fp16 transposed weights [mm][n][k]
__device__ __half g_whT[3 * HH * DD];

// ---------------------------------------------------------------------------
// helpers
// ---------------------------------------------------------------------------
__device__ __forceinline__ void cp_async16(void* smem_dst, const void* gmem_src) {
    unsigned s = (unsigned)__cvta_generic_to_shared(smem_dst);
    asm volatile("cp.async.cg.shared.global [%0], [%1], 16;\n" :: "r"(s), "l"(gmem_src));
}
__device__ __forceinline__ void cp_async_commit() {
    asm volatile("cp.async.commit_group;\n");
}
// f16 m16n8k16, f32 accumulate
__device__ __forceinline__ void mmaf16(float* d, const unsigned* a, const unsigned* b2,
                                       const float* c) {
    asm volatile(
        "mma.sync.aligned.m16n8k16.row.col.f32.f16.f16.f32 "
        "{%0,%1,%2,%3}, {%4,%5,%6,%7}, {%8,%9}, {%10,%11,%12,%13};\n"
        : "=f"(d[0]), "=f"(d[1]), "=f"(d[2]), "=f"(d[3])
        : "r"(a[0]), "r"(a[1]), "r"(a[2]), "r"(a[3]),
          "r"(b2[0]), "r"(b2[1]),
          "f"(c[0]), "f"(c[1]), "f"(c[2]), "f"(c[3]));
}
__device__ __forceinline__ unsigned packh2(float lo, float hi) {
    __half2 h = __floats2half2_rn(lo, hi);
    return *(unsigned*)&h;
}
// 2^x on both fp16 halves, one MUFU op
__device__ __forceinline__ unsigned ex2h2(unsigned x) {
    unsigned r;
    asm("ex2.approx.f16x2 %0, %1;" : "=r"(r) : "r"(x));
    return r;
}
// ldmatrix x4: 4 B-fragments (8x8 b16 each) in one instruction
__device__ __forceinline__ void ldsm4(unsigned* r, unsigned saddr) {
    asm volatile("ldmatrix.sync.aligned.m8n8.x4.shared.b16 {%0,%1,%2,%3}, [%4];\n"
                 : "=r"(r[0]), "=r"(r[1]), "=r"(r[2]), "=r"(r[3]) : "r"(saddr));
}

// ---------------------------------------------------------------------------
// Kernel 0: W -> fp16 transposed [mm][n][k]. 147456 elems, trivial.
// ---------------------------------------------------------------------------
__global__ void wconv_kernel(const float* __restrict__ Wq,
                             const float* __restrict__ Wk,
                             const float* __restrict__ Wv)
{
    int id = blockIdx.x * 256 + threadIdx.x;
    int k = id % DD;
    int rem = id / DD;
    int n = rem & 63;
    int mm = rem >> 6;
    const float* W = (mm == 0) ? Wq : (mm == 1) ? Wk : Wv;
    g_whT[(size_t)mm * HH * DD + (size_t)n * DD + k] = __float2half_rn(W[(size_t)k * HH + n]);
}

// ---------------------------------------------------------------------------
// Kernel 1: fused Q/K/V projection, fp16 m16n8k16 (R10 structure; Q prescale
// now QSCALE = 0.125*log2e).
// ---------------------------------------------------------------------------
__global__ void __launch_bounds__(256, 2) proj_kernel(
    const float* __restrict__ x,
    const float* __restrict__ bq, const float* __restrict__ bk,
    const float* __restrict__ bv)
{
    extern __shared__ __half smh[];
    __half* xsm = smh;                 // [2][64][PLDH]
    __half* wsm = smh + 2 * XBUF;      // [2][3][64][PLDH]

    const int tid  = threadIdx.x;
    const int warp = tid >> 5;
    const int lane = tid & 31;
    const int g    = lane >> 2;
    const int tig  = lane & 3;
    const int rg   = warp & 3;
    const int ch   = warp >> 2;
    const size_t row0 = (size_t)blockIdx.x * 64;

    const int lrow = tid >> 4;
    const int lc4  = tid & 15;

    float cacc[12][4];
#pragma unroll
    for (int j = 0; j < 12; j++)
#pragma unroll
        for (int i = 0; i < 4; i++) cacc[j][i] = 0.0f;

    uint2 ph[4];

#define LDX(kc)                                                                     \
    do {                                                                            \
        _Pragma("unroll")                                                           \
        for (int i = 0; i < 4; i++) {                                               \
            int row = lrow + i * 16;                                                \
            float4 v = *(const float4*)(x + (row0 + row) * DD + (kc) * 64 + lc4 * 4); \
            ph[i].x = packh2(v.x, v.y);                                             \
            ph[i].y = packh2(v.z, v.w);                                             \
        }                                                                           \
    } while (0)

#define STX(buf)                                                                    \
    do {                                                                            \
        _Pragma("unroll")                                                           \
        for (int i = 0; i < 4; i++) {                                               \
            int row = lrow + i * 16;                                                \
            *(uint2*)(xsm + (buf) * XBUF + row * PLDH + lc4 * 4) = ph[i];           \
        }                                                                           \
    } while (0)

#define LDW(kc, buf)                                                                \
    do {                                                                            \
        _Pragma("unroll")                                                           \
        for (int u = 0; u < 6; u++) {                                               \
            int t = tid + u * 256;                                                  \
            int mm = t >> 9, rem = t & 511, n = rem >> 3, c16 = rem & 7;            \
            cp_async16(wsm + (buf) * WBUF + mm * (64 * PLDH) + n * PLDH + c16 * 8,  \
                       g_whT + (size_t)mm * HH * DD + (size_t)n * DD + (kc) * 64 + c16 * 8); \
        }                                                                           \
        cp_async_commit();                                                          \
    } while (0)

    LDX(0);
    LDW(0, 0);
    STX(0);
    LDX(1);

    for (int kc = 0; kc < DD / 64; kc++) {
        const int cur = kc & 1;
        const int nxt = cur ^ 1;

        asm volatile("cp.async.wait_group 0;\n");
        __syncthreads();

        if (kc < DD / 64 - 1) {
            LDW(kc + 1, nxt);
            STX(nxt);
        }

        const __half* xs = xsm + cur * XBUF + rg * 16 * PLDH;
        unsigned a[4][4];
#pragma unroll
        for (int kk = 0; kk < 4; kk++) {
            a[kk][0] = *(const unsigned*)(xs + (size_t)g * PLDH + 16 * kk + 2 * tig);
            a[kk][1] = *(const unsigned*)(xs + (size_t)(g + 8) * PLDH + 16 * kk + 2 * tig);
            a[kk][2] = *(const unsigned*)(xs + (size_t)g * PLDH + 16 * kk + 2 * tig + 8);
            a[kk][3] = *(const unsigned*)(xs + (size_t)(g + 8) * PLDH + 16 * kk + 2 * tig + 8);
        }
#pragma unroll
        for (int j = 0; j < 12; j++) {
            int jj = ch * 12 + j;
            int mm = jj >> 3, nt = jj & 7;
            const __half* wt = wsm + cur * WBUF + mm * (64 * PLDH) + (nt * 8 + g) * PLDH;
#pragma unroll
            for (int kk = 0; kk < 4; kk++) {
                unsigned b2[2];
                b2[0] = *(const unsigned*)(wt + 16 * kk + 2 * tig);
                b2[1] = *(const unsigned*)(wt + 16 * kk + 2 * tig + 8);
                mmaf16(cacc[j], a[kk], b2, cacc[j]);
            }
        }

        if (kc < DD / 64 - 2) LDX(kc + 2);
    }

    const size_t rgg  = row0 + rg * 16 + g;
    const size_t rgg8 = rgg + 8;
#pragma unroll
    for (int j = 0; j < 12; j++) {
        int jj = ch * 12 + j;
        int mm = jj >> 3;
        int col = (jj & 7) * 8 + 2 * tig;
        if (mm == 0) {
            float b0 = bq[col], b1 = bq[col + 1];
            __half2 v0 = __floats2half2_rn(QSCALE * (cacc[j][0] + b0), QSCALE * (cacc[j][1] + b1));
            __half2 v8 = __floats2half2_rn(QSCALE * (cacc[j][2] + b0), QSCALE * (cacc[j][3] + b1));
            *(__half2*)(g_q + rgg * HH + col)  = v0;
            *(__half2*)(g_q + rgg8 * HH + col) = v8;
        } else if (mm == 1) {
            float b0 = bk[col], b1 = bk[col + 1];
            __half2 v0 = __floats2half2_rn(cacc[j][0] + b0, cacc[j][1] + b1);
            __half2 v8 = __floats2half2_rn(cacc[j][2] + b0, cacc[j][3] + b1);
            *(__half2*)(g_k + rgg * HH + col)  = v0;
            *(__half2*)(g_k + rgg8 * HH + col) = v8;
        } else {
            float b0 = bv[col], b1 = bv[col + 1];
            size_t bofs = (rgg >> 12) * (size_t)HH * NN;
            size_t n0 = rgg & 4095, n8 = rgg8 & 4095;
            g_vT[bofs + (size_t)col * NN + n0]       = __float2half_rn(cacc[j][0] + b0);
            g_vT[bofs + (size_t)(col + 1) * NN + n0] = __float2half_rn(cacc[j][1] + b1);
            g_vT[bofs + (size_t)col * NN + n8]       = __float2half_rn(cacc[j][2] + b0);
            g_vT[bofs + (size_t)(col + 1) * NN + n8] = __float2half_rn(cacc[j][3] + b1);
        }
    }
#undef LDX
#undef STX
#undef LDW
}

// ---------------------------------------------------------------------------
// Kernel 2: flash attention. S for all 64 keys first (8 independent mma
// chains), then pack+ex2.f16x2 (half the MUFU ops, zero exp FMULs), then PV.
// ---------------------------------------------------------------------------
__global__ void __launch_bounds__(256, 2) attn_kernel(float* __restrict__ out)
{
    extern __shared__ __half smh[];
    __half* s_k = smh;                  // [2][64][LDH]
    __half* s_v = smh + 2 * TILEH;      // [2][64][LDH]  (V^T: rows=d, cols=keys)

    const int tid  = threadIdx.x;
    const int warp = tid >> 5;
    const int lane = tid & 31;
    const int g    = lane >> 2;
    const int tig  = lane & 3;
    const int mat  = lane >> 3;         // ldmatrix matrix id 0..3
    const int r8   = lane & 7;          // ldmatrix row within matrix
    const int b    = blockIdx.y;
    const int q0   = blockIdx.x * 128;

    const unsigned sk_u = (unsigned)__cvta_generic_to_shared(s_k);
    const unsigned sv_u = (unsigned)__cvta_generic_to_shared(s_v);

    // ---- persistent Q A-fragments (fp16, QSCALE pre-folded) ----
    const __half* qbase = g_q + (size_t)(b * NN + q0 + warp * 16) * HH;
    unsigned qa[4][4];
#pragma unroll
    for (int kk = 0; kk < 4; kk++) {
        qa[kk][0] = *(const unsigned*)(qbase + (size_t)g * HH + 16 * kk + 2 * tig);
        qa[kk][1] = *(const unsigned*)(qbase + (size_t)(g + 8) * HH + 16 * kk + 2 * tig);
        qa[kk][2] = *(const unsigned*)(qbase + (size_t)g * HH + 16 * kk + 2 * tig + 8);
        qa[kk][3] = *(const unsigned*)(qbase + (size_t)(g + 8) * HH + 16 * kk + 2 * tig + 8);
    }

    unsigned onesb2[2];
    onesb2[0] = onesb2[1] = (g == 0) ? 0x3C003C00u : 0u;

    float oacc[8][4];
#pragma unroll
    for (int j = 0; j < 8; j++)
#pragma unroll
        for (int i = 0; i < 4; i++) oacc[j][i] = 0.0f;
    float lacc[4] = {0.f, 0.f, 0.f, 0.f};

    const __half* gk  = g_k + (size_t)b * NN * HH;
    const __half* gvT = g_vT + (size_t)b * HH * NN;
#pragma unroll
    for (int u = 0; u < 2; u++) {
        int id = tid + u * 256;
        int row = id >> 3, c16 = id & 7;
        cp_async16(s_k + row * LDH + c16 * 8, gk + (size_t)row * HH + c16 * 8);
        cp_async16(s_v + row * LDH + c16 * 8, gvT + (size_t)row * NN + c16 * 8);
    }
    cp_async_commit();

    for (int kb = 0; kb < NN / 64; kb++) {
        const int cur = kb & 1;
        const int nxt = cur ^ 1;

        asm volatile("cp.async.wait_group 0;\n");
        __syncthreads();

        if (kb < NN / 64 - 1) {
            const int k0n = (kb + 1) * 64;
#pragma unroll
            for (int u = 0; u < 2; u++) {
                int id = tid + u * 256;
                int row = id >> 3, c16 = id & 7;
                cp_async16(s_k + nxt * TILEH + row * LDH + c16 * 8,
                           gk + (size_t)(k0n + row) * HH + c16 * 8);
                cp_async16(s_v + nxt * TILEH + row * LDH + c16 * 8,
                           gvT + (size_t)row * NN + k0n + c16 * 8);
            }
            cp_async_commit();
        }

        const unsigned kbase = sk_u + cur * TILEH * 2;
        const unsigned vbase = sv_u + cur * TILEH * 2;

        // ---- S = Q @ K^T for ALL 64 keys: 8 independent accumulator chains ----
        const unsigned ka = kbase +
            ((unsigned)((((mat >> 1) << 3) + r8) * LDH + ((mat & 1) << 3)) << 1);
        float sacc[8][4];
#pragma unroll
        for (int c = 0; c < 8; c++)
#pragma unroll
            for (int i = 0; i < 4; i++) sacc[c][i] = 0.0f;

#pragma unroll
        for (int kk = 0; kk < 4; kk++) {
#pragma unroll
            for (int c2 = 0; c2 < 4; c2++) {      // 16 keys per x4
                unsigned kf[4];
                ldsm4(kf, ka + ((unsigned)(c2 * 16 * LDH + kk * 16) << 1));
                mmaf16(sacc[2 * c2],     qa[kk], kf + 0, sacc[2 * c2]);
                mmaf16(sacc[2 * c2 + 1], qa[kk], kf + 2, sacc[2 * c2 + 1]);
            }
        }

        // ---- P = 2^(S) : pack to half2, one ex2.f16x2 per pair ----
        unsigned paf[4][4];
#pragma unroll
        for (int cp = 0; cp < 4; cp++) {
            float* s0 = sacc[2 * cp];
            float* s1 = sacc[2 * cp + 1];
            paf[cp][0] = ex2h2(packh2(s0[0], s0[1]));
            paf[cp][1] = ex2h2(packh2(s0[2], s0[3]));
            paf[cp][2] = ex2h2(packh2(s1[0], s1[1]));
            paf[cp][3] = ex2h2(packh2(s1[2], s1[3]));
        }

        // ---- l += P @ ones ----
#pragma unroll
        for (int cp = 0; cp < 4; cp++)
            mmaf16(lacc, paf[cp], onesb2, lacc);

        // ---- O += P @ V : per j two x4 (keys 0..31, 32..63), 4 mma ----
        const unsigned va = vbase + ((unsigned)(r8 * LDH + mat * 8) << 1);
#pragma unroll
        for (int j = 0; j < 8; j++) {
            unsigned vf0[4], vf1[4];
            ldsm4(vf0, va + ((unsigned)(j * 8 * LDH) << 1));
            ldsm4(vf1, va + ((unsigned)(j * 8 * LDH + 32) << 1));
            mmaf16(oacc[j], paf[0], vf0 + 0, oacc[j]);
            mmaf16(oacc[j], paf[1], vf0 + 2, oacc[j]);
            mmaf16(oacc[j], paf[2], vf1 + 0, oacc[j]);
            mmaf16(oacc[j], paf[3], vf1 + 2, oacc[j]);
        }
    }

    float lg  = __shfl_sync(0xffffffffu, lacc[0], lane & ~3);
    float lg8 = __shfl_sync(0xffffffffu, lacc[2], lane & ~3);
    float inv0 = 1.0f / lg;
    float inv8 = 1.0f / lg8;

    float* orow0 = out + (size_t)(b * NN + q0 + warp * 16 + g) * HH;
    float* orow8 = out + (size_t)(b * NN + q0 + warp * 16 + g + 8) * HH;
#pragma unroll
    for (int j = 0; j < 8; j++) {
        float2 v0 = make_float2(oacc[j][0] * inv0, oacc[j][1] * inv0);
        float2 v8 = make_float2(oacc[j][2] * inv8, oacc[j][3] * inv8);
        *(float2*)(orow0 + j * 8 + 2 * tig) = v0;
        *(float2*)(orow8 + j * 8 + 2 * tig) = v8;
    }
}

// ---------------------------------------------------------------------------
extern "C" void kernel_launch(void* const* d_in, const int* in_sizes, int n_in,
                              void* d_out, int out_size)
{
    const float* x  = (const float*)d_in[0];
    const float* Wq = (const float*)d_in[1];
    const float* bq = (const float*)d_in[2];
    const float* Wk = (const float*)d_in[3];
    const float* bk = (const float*)d_in[4];
    const float* Wv = (const float*)d_in[5];
    const float* bv = (const float*)d_in[6];
    float* out = (float*)d_out;

    const int smem_proj = (2 * XBUF + 2 * WBUF) * (int)sizeof(__half);   // 73728
    const int smem_attn = 4 * TILEH * (int)sizeof(__half);               // 36864

    (void)cudaFuncSetAttribute(proj_kernel, cudaFuncAttributeMaxDynamicSharedMemorySize, smem_proj);
    (void)cudaFuncSetAttribute(attn_kernel, cudaFuncAttributeMaxDynamicSharedMemorySize, smem_attn);

    wconv_kernel<<<(3 * HH * DD) / 256, 256>>>(Wq, Wk, Wv);
    proj_kernel<<<(BB * NN) / 64, 256, smem_proj>>>(x, bq, bk, bv);
    attn_kernel<<<dim3(NN / 128, BB), 256, smem_attn>>>(out);
}

// round 14
// speedup vs baseline: 8.5814x; 1.0670x over previous
#include <cuda_runtime.h>
#include <cuda_fp16.h>
#include <cstdint>
#include <mma.h>

// Problem constants
#define BB 8
#define NN 4096
#define DD 768
#define HH 64

// attn smem leading dim (halves): 72 -> bank = 4g+tig, conflict-free
#define LDH 72
#define TILEH (64 * LDH)

// proj smem tiles (halves)
#define PLDH 72
#define XBUF (64 * PLDH)
#define WBUF (3 * 64 * PLDH)

// Q prescale: 1/sqrt(64) * log2(e), folded so attn can use ex2 directly
#define QSCALE 0.18033688f

// Device scratch: fp16 projections. Q has QSCALE pre-folded. V stored transposed [b][d][n].
__device__ __half g_q[BB * NN * HH];
__device__ __half g_k[BB * NN * HH];
__device__ __half g_vT[BB * HH * NN];
__device__ __half g_whT[3 * HH * DD];

// ---------------------------------------------------------------------------
// helpers
// ---------------------------------------------------------------------------
__device__ __forceinline__ void cp_async16(void* smem_dst, const void* gmem_src) {
    unsigned s = (unsigned)__cvta_generic_to_shared(smem_dst);
    asm volatile("cp.async.cg.shared.global [%0], [%1], 16;\n" :: "r"(s), "l"(gmem_src));
}
__device__ __forceinline__ void cp_async_commit() {
    asm volatile("cp.async.commit_group;\n");
}
__device__ __forceinline__ void mmaf16(float* d, const unsigned* a, const unsigned* b2,
                                       const float* c) {
    asm volatile(
        "mma.sync.aligned.m16n8k16.row.col.f32.f16.f16.f32 "
        "{%0,%1,%2,%3}, {%4,%5,%6,%7}, {%8,%9}, {%10,%11,%12,%13};\n"
        : "=f"(d[0]), "=f"(d[1]), "=f"(d[2]), "=f"(d[3])
        : "r"(a[0]), "r"(a[1]), "r"(a[2]), "r"(a[3]),
          "r"(b2[0]), "r"(b2[1]),
          "f"(c[0]), "f"(c[1]), "f"(c[2]), "f"(c[3]));
}
__device__ __forceinline__ unsigned packh2(float lo, float hi) {
    __half2 h = __floats2half2_rn(lo, hi);
    return *(unsigned*)&h;
}
__device__ __forceinline__ unsigned ex2h2(unsigned x) {
    unsigned r;
    asm("ex2.approx.f16x2 %0, %1;" : "=r"(r) : "r"(x));
    return r;
}
__device__ __forceinline__ void ldsm4(unsigned* r, unsigned saddr) {
    asm volatile("ldmatrix.sync.aligned.m8n8.x4.shared.b16 {%0,%1,%2,%3}, [%4];\n"
                 : "=r"(r[0]), "=r"(r[1]), "=r"(r[2]), "=r"(r[3]) : "r"(saddr));
}

// ---------------------------------------------------------------------------
// Kernel 0: W -> fp16 transposed [mm][n][k] (unchanged).
// ---------------------------------------------------------------------------
__global__ void wconv_kernel(const float* __restrict__ Wq,
                             const float* __restrict__ Wk,
                             const float* __restrict__ Wv)
{
    int id = blockIdx.x * 256 + threadIdx.x;
    int k = id % DD;
    int rem = id / DD;
    int n = rem & 63;
    int mm = rem >> 6;
    const float* W = (mm == 0) ? Wq : (mm == 1) ? Wk : Wv;
    g_whT[(size_t)mm * HH * DD + (size_t)n * DD + k] = __float2half_rn(W[(size_t)k * HH + n]);
}

// ---------------------------------------------------------------------------
// Kernel 1: fused Q/K/V projection, fp16 m16n8k16 (byte-identical to R12).
// ---------------------------------------------------------------------------
__global__ void __launch_bounds__(256, 2) proj_kernel(
    const float* __restrict__ x,
    const float* __restrict__ bq, const float* __restrict__ bk,
    const float* __restrict__ bv)
{
    extern __shared__ __half smh[];
    __half* xsm = smh;
    __half* wsm = smh + 2 * XBUF;

    const int tid  = threadIdx.x;
    const int warp = tid >> 5;
    const int lane = tid & 31;
    const int g    = lane >> 2;
    const int tig  = lane & 3;
    const int rg   = warp & 3;
    const int ch   = warp >> 2;
    const size_t row0 = (size_t)blockIdx.x * 64;

    const int lrow = tid >> 4;
    const int lc4  = tid & 15;

    float cacc[12][4];
#pragma unroll
    for (int j = 0; j < 12; j++)
#pragma unroll
        for (int i = 0; i < 4; i++) cacc[j][i] = 0.0f;

    uint2 ph[4];

#define LDX(kc)                                                                     \
    do {                                                                            \
        _Pragma("unroll")                                                           \
        for (int i = 0; i < 4; i++) {                                               \
            int row = lrow + i * 16;                                                \
            float4 v = *(const float4*)(x + (row0 + row) * DD + (kc) * 64 + lc4 * 4); \
            ph[i].x = packh2(v.x, v.y);                                             \
            ph[i].y = packh2(v.z, v.w);                                             \
        }                                                                           \
    } while (0)

#define STX(buf)                                                                    \
    do {                                                                            \
        _Pragma("unroll")                                                           \
        for (int i = 0; i < 4; i++) {                                               \
            int row = lrow + i * 16;                                                \
            *(uint2*)(xsm + (buf) * XBUF + row * PLDH + lc4 * 4) = ph[i];           \
        }                                                                           \
    } while (0)

#define LDW(kc, buf)                                                                \
    do {                                                                            \
        _Pragma("unroll")                                                           \
        for (int u = 0; u < 6; u++) {                                               \
            int t = tid + u * 256;                                                  \
            int mm = t >> 9, rem = t & 511, n = rem >> 3, c16 = rem & 7;            \
            cp_async16(wsm + (buf) * WBUF + mm * (64 * PLDH) + n * PLDH + c16 * 8,  \
                       g_whT + (size_t)mm * HH * DD + (size_t)n * DD + (kc) * 64 + c16 * 8); \
        }                                                                           \
        cp_async_commit();                                                          \
    } while (0)

    LDX(0);
    LDW(0, 0);
    STX(0);
    LDX(1);

    for (int kc = 0; kc < DD / 64; kc++) {
        const int cur = kc & 1;
        const int nxt = cur ^ 1;

        asm volatile("cp.async.wait_group 0;\n");
        __syncthreads();

        if (kc < DD / 64 - 1) {
            LDW(kc + 1, nxt);
            STX(nxt);
        }

        const __half* xs = xsm + cur * XBUF + rg * 16 * PLDH;
        unsigned a[4][4];
#pragma unroll
        for (int kk = 0; kk < 4; kk++) {
            a[kk][0] = *(const unsigned*)(xs + (size_t)g * PLDH + 16 * kk + 2 * tig);
            a[kk][1] = *(const unsigned*)(xs + (size_t)(g + 8) * PLDH + 16 * kk + 2 * tig);
            a[kk][2] = *(const unsigned*)(xs + (size_t)g * PLDH + 16 * kk + 2 * tig + 8);
            a[kk][3] = *(const unsigned*)(xs + (size_t)(g + 8) * PLDH + 16 * kk + 2 * tig + 8);
        }
#pragma unroll
        for (int j = 0; j < 12; j++) {
            int jj = ch * 12 + j;
            int mm = jj >> 3, nt = jj & 7;
            const __half* wt = wsm + cur * WBUF + mm * (64 * PLDH) + (nt * 8 + g) * PLDH;
#pragma unroll
            for (int kk = 0; kk < 4; kk++) {
                unsigned b2[2];
                b2[0] = *(const unsigned*)(wt + 16 * kk + 2 * tig);
                b2[1] = *(const unsigned*)(wt + 16 * kk + 2 * tig + 8);
                mmaf16(cacc[j], a[kk], b2, cacc[j]);
            }
        }

        if (kc < DD / 64 - 2) LDX(kc + 2);
    }

    const size_t rgg  = row0 + rg * 16 + g;
    const size_t rgg8 = rgg + 8;
#pragma unroll
    for (int j = 0; j < 12; j++) {
        int jj = ch * 12 + j;
        int mm = jj >> 3;
        int col = (jj & 7) * 8 + 2 * tig;
        if (mm == 0) {
            float b0 = bq[col], b1 = bq[col + 1];
            __half2 v0 = __floats2half2_rn(QSCALE * (cacc[j][0] + b0), QSCALE * (cacc[j][1] + b1));
            __half2 v8 = __floats2half2_rn(QSCALE * (cacc[j][2] + b0), QSCALE * (cacc[j][3] + b1));
            *(__half2*)(g_q + rgg * HH + col)  = v0;
            *(__half2*)(g_q + rgg8 * HH + col) = v8;
        } else if (mm == 1) {
            float b0 = bk[col], b1 = bk[col + 1];
            __half2 v0 = __floats2half2_rn(cacc[j][0] + b0, cacc[j][1] + b1);
            __half2 v8 = __floats2half2_rn(cacc[j][2] + b0, cacc[j][3] + b1);
            *(__half2*)(g_k + rgg * HH + col)  = v0;
            *(__half2*)(g_k + rgg8 * HH + col) = v8;
        } else {
            float b0 = bv[col], b1 = bv[col + 1];
            size_t bofs = (rgg >> 12) * (size_t)HH * NN;
            size_t n0 = rgg & 4095, n8 = rgg8 & 4095;
            g_vT[bofs + (size_t)col * NN + n0]       = __float2half_rn(cacc[j][0] + b0);
            g_vT[bofs + (size_t)(col + 1) * NN + n0] = __float2half_rn(cacc[j][1] + b1);
            g_vT[bofs + (size_t)col * NN + n8]       = __float2half_rn(cacc[j][2] + b0);
            g_vT[bofs + (size_t)(col + 1) * NN + n8] = __float2half_rn(cacc[j][3] + b1);
        }
    }
#undef LDX
#undef STX
#undef LDW
}

// ---------------------------------------------------------------------------
// Kernel 2: flash attention, software-pipelined: per iteration issue
// S(kb) -> PV(kb-1) -> exp(kb). PV uses paf from the PREVIOUS block, so the
// S mma chain and ex2 latency are hidden behind PV issue. V uses a 3-stage
// ring (PV reads block kb-1 while prefetch writes kb+1); K stays 2-stage.
// ---------------------------------------------------------------------------
__global__ void __launch_bounds__(256, 2) attn_kernel(float* __restrict__ out)
{
    extern __shared__ __half smh[];
    __half* s_k = smh;                  // [2][64][LDH]
    __half* s_v = smh + 2 * TILEH;      // [3][64][LDH]  (V^T: rows=d, cols=keys)

    const int tid  = threadIdx.x;
    const int warp = tid >> 5;
    const int lane = tid & 31;
    const int g    = lane >> 2;
    const int tig  = lane & 3;
    const int mat  = lane >> 3;
    const int r8   = lane & 7;
    const int b    = blockIdx.y;
    const int q0   = blockIdx.x * 128;

    const unsigned sk_u = (unsigned)__cvta_generic_to_shared(s_k);
    const unsigned sv_u = (unsigned)__cvta_generic_to_shared(s_v);

    // ---- persistent Q A-fragments (fp16, QSCALE pre-folded) ----
    const __half* qbase = g_q + (size_t)(b * NN + q0 + warp * 16) * HH;
    unsigned qa[4][4];
#pragma unroll
    for (int kk = 0; kk < 4; kk++) {
        qa[kk][0] = *(const unsigned*)(qbase + (size_t)g * HH + 16 * kk + 2 * tig);
        qa[kk][1] = *(const unsigned*)(qbase + (size_t)(g + 8) * HH + 16 * kk + 2 * tig);
        qa[kk][2] = *(const unsigned*)(qbase + (size_t)g * HH + 16 * kk + 2 * tig + 8);
        qa[kk][3] = *(const unsigned*)(qbase + (size_t)(g + 8) * HH + 16 * kk + 2 * tig + 8);
    }

    unsigned onesb2[2];
    onesb2[0] = onesb2[1] = (g == 0) ? 0x3C003C00u : 0u;

    float oacc[8][4];
#pragma unroll
    for (int j = 0; j < 8; j++)
#pragma unroll
        for (int i = 0; i < 4; i++) oacc[j][i] = 0.0f;
    float lacc[4] = {0.f, 0.f, 0.f, 0.f};
    unsigned paf[4][4];                 // P of previous block, lives across iters

    const __half* gk  = g_k + (size_t)b * NN * HH;
    const __half* gvT = g_vT + (size_t)b * HH * NN;

#define PRE(kb_, kbuf_, vstage_)                                                    \
    do {                                                                            \
        _Pragma("unroll")                                                           \
        for (int u = 0; u < 2; u++) {                                               \
            int id = tid + u * 256;                                                 \
            int row = id >> 3, c16 = id & 7;                                        \
            cp_async16(s_k + (kbuf_) * TILEH + row * LDH + c16 * 8,                 \
                       gk + (size_t)((kb_) * 64 + row) * HH + c16 * 8);             \
            cp_async16(s_v + (vstage_) * TILEH + row * LDH + c16 * 8,               \
                       gvT + (size_t)row * NN + (kb_) * 64 + c16 * 8);              \
        }                                                                           \
        cp_async_commit();                                                          \
    } while (0)

// PV body for block whose P is in paf and whose V tile is at stage vs_
#define PV(vs_)                                                                     \
    do {                                                                            \
        const unsigned va = sv_u + (unsigned)(vs_) * (TILEH * 2) +                  \
                            ((unsigned)(r8 * LDH + mat * 8) << 1);                  \
        _Pragma("unroll")                                                           \
        for (int cp = 0; cp < 4; cp++) mmaf16(lacc, paf[cp], onesb2, lacc);         \
        _Pragma("unroll")                                                           \
        for (int j = 0; j < 8; j++) {                                               \
            unsigned vf0[4], vf1[4];                                                \
            ldsm4(vf0, va + ((unsigned)(j * 8 * LDH) << 1));                        \
            ldsm4(vf1, va + ((unsigned)(j * 8 * LDH + 32) << 1));                   \
            mmaf16(oacc[j], paf[0], vf0 + 0, oacc[j]);                              \
            mmaf16(oacc[j], paf[1], vf0 + 2, oacc[j]);                              \
            mmaf16(oacc[j], paf[2], vf1 + 0, oacc[j]);                              \
            mmaf16(oacc[j], paf[3], vf1 + 2, oacc[j]);                              \
        }                                                                           \
    } while (0)

    PRE(0, 0, 0);

    int vs_cur = 0;                     // V stage of the current block

    for (int kb = 0; kb < NN / 64; kb++) {
        const int kcur = kb & 1;
        const int vs_nxt  = (vs_cur == 2) ? 0 : vs_cur + 1;
        const int vs_prev = (vs_cur == 0) ? 2 : vs_cur - 1;

        asm volatile("cp.async.wait_group 0;\n");
        __syncthreads();

        if (kb < NN / 64 - 1)
            PRE(kb + 1, kcur ^ 1, vs_nxt);

        // ---- S(kb): all 64 keys, 8 independent chains ----
        const unsigned ka = sk_u + (unsigned)kcur * (TILEH * 2) +
            ((unsigned)((((mat >> 1) << 3) + r8) * LDH + ((mat & 1) << 3)) << 1);
        float sacc[8][4];
#pragma unroll
        for (int c = 0; c < 8; c++)
#pragma unroll
            for (int i = 0; i < 4; i++) sacc[c][i] = 0.0f;

#pragma unroll
        for (int kk = 0; kk < 4; kk++) {
#pragma unroll
            for (int c2 = 0; c2 < 4; c2++) {
                unsigned kf[4];
                ldsm4(kf, ka + ((unsigned)(c2 * 16 * LDH + kk * 16) << 1));
                mmaf16(sacc[2 * c2],     qa[kk], kf + 0, sacc[2 * c2]);
                mmaf16(sacc[2 * c2 + 1], qa[kk], kf + 2, sacc[2 * c2 + 1]);
            }
        }

        // ---- PV(kb-1): fills the S-chain latency; no deps on S(kb) ----
        if (kb > 0)
            PV(vs_prev);

        // ---- exp(kb) -> paf for next iteration ----
#pragma unroll
        for (int cp = 0; cp < 4; cp++) {
            float* s0 = sacc[2 * cp];
            float* s1 = sacc[2 * cp + 1];
            paf[cp][0] = ex2h2(packh2(s0[0], s0[1]));
            paf[cp][1] = ex2h2(packh2(s0[2], s0[3]));
            paf[cp][2] = ex2h2(packh2(s1[0], s1[1]));
            paf[cp][3] = ex2h2(packh2(s1[2], s1[3]));
        }

        vs_cur = vs_nxt;
    }

    // ---- peeled PV for the last block (its V stage = stage of block 63) ----
    {
        const int vs_last = (vs_cur == 0) ? 2 : vs_cur - 1;
        PV(vs_last);
    }

    float lg  = __shfl_sync(0xffffffffu, lacc[0], lane & ~3);
    float lg8 = __shfl_sync(0xffffffffu, lacc[2], lane & ~3);
    float inv0 = 1.0f / lg;
    float inv8 = 1.0f / lg8;

    float* orow0 = out + (size_t)(b * NN + q0 + warp * 16 + g) * HH;
    float* orow8 = out + (size_t)(b * NN + q0 + warp * 16 + g + 8) * HH;
#pragma unroll
    for (int j = 0; j < 8; j++) {
        float2 v0 = make_float2(oacc[j][0] * inv0, oacc[j][1] * inv0);
        float2 v8 = make_float2(oacc[j][2] * inv8, oacc[j][3] * inv8);
        *(float2*)(orow0 + j * 8 + 2 * tig) = v0;
        *(float2*)(orow8 + j * 8 + 2 * tig) = v8;
    }
#undef PRE
#undef PV
}

// ---------------------------------------------------------------------------
extern "C" void kernel_launch(void* const* d_in, const int* in_sizes, int n_in,
                              void* d_out, int out_size)
{
    const float* x  = (const float*)d_in[0];
    const float* Wq = (const float*)d_in[1];
    const float* bq = (const float*)d_in[2];
    const float* Wk = (const float*)d_in[3];
    const float* bk = (const float*)d_in[4];
    const float* Wv = (const float*)d_in[5];
    const float* bv = (const float*)d_in[6];
    float* out = (float*)d_out;

    const int smem_proj = (2 * XBUF + 2 * WBUF) * (int)sizeof(__half);   // 73728
    const int smem_attn = 5 * TILEH * (int)sizeof(__half);               // 46080

    (void)cudaFuncSetAttribute(proj_kernel, cudaFuncAttributeMaxDynamicSharedMemorySize, smem_proj);
    (void)cudaFuncSetAttribute(attn_kernel, cudaFuncAttributeMaxDynamicSharedMemorySize, smem_attn);

    wconv_kernel<<<(3 * HH * DD) / 256, 256>>>(Wq, Wk, Wv);
    proj_kernel<<<(BB * NN) / 64, 256, smem_proj>>>(x, bq, bk, bv);
    attn_kernel<<<dim3(NN / 128, BB), 256, smem_attn>>>(out);
}

// round 15
// speedup vs baseline: 8.5829x; 1.0002x over previous
#include <cuda_runtime.h>
#include <cuda_fp16.h>
#include <cstdint>
#include <mma.h>

// Problem constants
#define BB 8
#define NN 4096
#define DD 768
#define HH 64

// attn smem leading dim (halves): 72 -> bank = 4g+tig, conflict-free
#define LDH 72
#define TILEH (64 * LDH)

// proj smem tiles (halves)
#define PLDH 72
#define XBUF (64 * PLDH)
#define WBUF (3 * 64 * PLDH)

// Q prescale: 1/sqrt(64) * log2(e), folded so attn can use ex2 directly
#define QSCALE 0.18033688f

// Device scratch: fp16 projections. Q has QSCALE pre-folded. V stored transposed [b][d][n].
__device__ __half g_q[BB * NN * HH];
__device__ __half g_k[BB * NN * HH];
__device__ __half g_vT[BB * HH * NN];
__device__ __half g_whT[3 * HH * DD];

// ---------------------------------------------------------------------------
// helpers
// ---------------------------------------------------------------------------
__device__ __forceinline__ void cp_async16(void* smem_dst, const void* gmem_src) {
    unsigned s = (unsigned)__cvta_generic_to_shared(smem_dst);
    asm volatile("cp.async.cg.shared.global [%0], [%1], 16;\n" :: "r"(s), "l"(gmem_src));
}
__device__ __forceinline__ void cp_async_commit() {
    asm volatile("cp.async.commit_group;\n");
}
// f16 m16n8k16, f32 accumulate
__device__ __forceinline__ void mmaf16(float* d, const unsigned* a, const unsigned* b2,
                                       const float* c) {
    asm volatile(
        "mma.sync.aligned.m16n8k16.row.col.f32.f16.f16.f32 "
        "{%0,%1,%2,%3}, {%4,%5,%6,%7}, {%8,%9}, {%10,%11,%12,%13};\n"
        : "=f"(d[0]), "=f"(d[1]), "=f"(d[2]), "=f"(d[3])
        : "r"(a[0]), "r"(a[1]), "r"(a[2]), "r"(a[3]),
          "r"(b2[0]), "r"(b2[1]),
          "f"(c[0]), "f"(c[1]), "f"(c[2]), "f"(c[3]));
}
// f16 m16n8k16, f16 accumulate (S matrix)
__device__ __forceinline__ void mmaf16h(unsigned* d, const unsigned* a, const unsigned* b2,
                                        const unsigned* c) {
    asm volatile(
        "mma.sync.aligned.m16n8k16.row.col.f16.f16.f16.f16 "
        "{%0,%1}, {%2,%3,%4,%5}, {%6,%7}, {%8,%9};\n"
        : "=r"(d[0]), "=r"(d[1])
        : "r"(a[0]), "r"(a[1]), "r"(a[2]), "r"(a[3]),
          "r"(b2[0]), "r"(b2[1]),
          "r"(c[0]), "r"(c[1]));
}
__device__ __forceinline__ unsigned packh2(float lo, float hi) {
    __half2 h = __floats2half2_rn(lo, hi);
    return *(unsigned*)&h;
}
__device__ __forceinline__ unsigned ex2h2(unsigned x) {
    unsigned r;
    asm("ex2.approx.f16x2 %0, %1;" : "=r"(r) : "r"(x));
    return r;
}
__device__ __forceinline__ unsigned hadd2u(unsigned a, unsigned b) {
    __half2 r = __hadd2(*(__half2*)&a, *(__half2*)&b);
    return *(unsigned*)&r;
}
__device__ __forceinline__ void ldsm4(unsigned* r, unsigned saddr) {
    asm volatile("ldmatrix.sync.aligned.m8n8.x4.shared.b16 {%0,%1,%2,%3}, [%4];\n"
                 : "=r"(r[0]), "=r"(r[1]), "=r"(r[2]), "=r"(r[3]) : "r"(saddr));
}

// ---------------------------------------------------------------------------
// Kernel 0: W -> fp16 transposed [mm][n][k] (unchanged).
// ---------------------------------------------------------------------------
__global__ void wconv_kernel(const float* __restrict__ Wq,
                             const float* __restrict__ Wk,
                             const float* __restrict__ Wv)
{
    int id = blockIdx.x * 256 + threadIdx.x;
    int k = id % DD;
    int rem = id / DD;
    int n = rem & 63;
    int mm = rem >> 6;
    const float* W = (mm == 0) ? Wq : (mm == 1) ? Wk : Wv;
    g_whT[(size_t)mm * HH * DD + (size_t)n * DD + k] = __float2half_rn(W[(size_t)k * HH + n]);
}

// ---------------------------------------------------------------------------
// Kernel 1: fused Q/K/V projection, fp16 m16n8k16 (byte-identical to R12).
// ---------------------------------------------------------------------------
__global__ void __launch_bounds__(256, 2) proj_kernel(
    const float* __restrict__ x,
    const float* __restrict__ bq, const float* __restrict__ bk,
    const float* __restrict__ bv)
{
    extern __shared__ __half smh[];
    __half* xsm = smh;
    __half* wsm = smh + 2 * XBUF;

    const int tid  = threadIdx.x;
    const int warp = tid >> 5;
    const int lane = tid & 31;
    const int g    = lane >> 2;
    const int tig  = lane & 3;
    const int rg   = warp & 3;
    const int ch   = warp >> 2;
    const size_t row0 = (size_t)blockIdx.x * 64;

    const int lrow = tid >> 4;
    const int lc4  = tid & 15;

    float cacc[12][4];
#pragma unroll
    for (int j = 0; j < 12; j++)
#pragma unroll
        for (int i = 0; i < 4; i++) cacc[j][i] = 0.0f;

    uint2 ph[4];

#define LDX(kc)                                                                     \
    do {                                                                            \
        _Pragma("unroll")                                                           \
        for (int i = 0; i < 4; i++) {                                               \
            int row = lrow + i * 16;                                                \
            float4 v = *(const float4*)(x + (row0 + row) * DD + (kc) * 64 + lc4 * 4); \
            ph[i].x = packh2(v.x, v.y);                                             \
            ph[i].y = packh2(v.z, v.w);                                             \
        }                                                                           \
    } while (0)

#define STX(buf)                                                                    \
    do {                                                                            \
        _Pragma("unroll")                                                           \
        for (int i = 0; i < 4; i++) {                                               \
            int row = lrow + i * 16;                                                \
            *(uint2*)(xsm + (buf) * XBUF + row * PLDH + lc4 * 4) = ph[i];           \
        }                                                                           \
    } while (0)

#define LDW(kc, buf)                                                                \
    do {                                                                            \
        _Pragma("unroll")                                                           \
        for (int u = 0; u < 6; u++) {                                               \
            int t = tid + u * 256;                                                  \
            int mm = t >> 9, rem = t & 511, n = rem >> 3, c16 = rem & 7;            \
            cp_async16(wsm + (buf) * WBUF + mm * (64 * PLDH) + n * PLDH + c16 * 8,  \
                       g_whT + (size_t)mm * HH * DD + (size_t)n * DD + (kc) * 64 + c16 * 8); \
        }                                                                           \
        cp_async_commit();                                                          \
    } while (0)

    LDX(0);
    LDW(0, 0);
    STX(0);
    LDX(1);

    for (int kc = 0; kc < DD / 64; kc++) {
        const int cur = kc & 1;
        const int nxt = cur ^ 1;

        asm volatile("cp.async.wait_group 0;\n");
        __syncthreads();

        if (kc < DD / 64 - 1) {
            LDW(kc + 1, nxt);
            STX(nxt);
        }

        const __half* xs = xsm + cur * XBUF + rg * 16 * PLDH;
        unsigned a[4][4];
#pragma unroll
        for (int kk = 0; kk < 4; kk++) {
            a[kk][0] = *(const unsigned*)(xs + (size_t)g * PLDH + 16 * kk + 2 * tig);
            a[kk][1] = *(const unsigned*)(xs + (size_t)(g + 8) * PLDH + 16 * kk + 2 * tig);
            a[kk][2] = *(const unsigned*)(xs + (size_t)g * PLDH + 16 * kk + 2 * tig + 8);
            a[kk][3] = *(const unsigned*)(xs + (size_t)(g + 8) * PLDH + 16 * kk + 2 * tig + 8);
        }
#pragma unroll
        for (int j = 0; j < 12; j++) {
            int jj = ch * 12 + j;
            int mm = jj >> 3, nt = jj & 7;
            const __half* wt = wsm + cur * WBUF + mm * (64 * PLDH) + (nt * 8 + g) * PLDH;
#pragma unroll
            for (int kk = 0; kk < 4; kk++) {
                unsigned b2[2];
                b2[0] = *(const unsigned*)(wt + 16 * kk + 2 * tig);
                b2[1] = *(const unsigned*)(wt + 16 * kk + 2 * tig + 8);
                mmaf16(cacc[j], a[kk], b2, cacc[j]);
            }
        }

        if (kc < DD / 64 - 2) LDX(kc + 2);
    }

    const size_t rgg  = row0 + rg * 16 + g;
    const size_t rgg8 = rgg + 8;
#pragma unroll
    for (int j = 0; j < 12; j++) {
        int jj = ch * 12 + j;
        int mm = jj >> 3;
        int col = (jj & 7) * 8 + 2 * tig;
        if (mm == 0) {
            float b0 = bq[col], b1 = bq[col + 1];
            __half2 v0 = __floats2half2_rn(QSCALE * (cacc[j][0] + b0), QSCALE * (cacc[j][1] + b1));
            __half2 v8 = __floats2half2_rn(QSCALE * (cacc[j][2] + b0), QSCALE * (cacc[j][3] + b1));
            *(__half2*)(g_q + rgg * HH + col)  = v0;
            *(__half2*)(g_q + rgg8 * HH + col) = v8;
        } else if (mm == 1) {
            float b0 = bk[col], b1 = bk[col + 1];
            __half2 v0 = __floats2half2_rn(cacc[j][0] + b0, cacc[j][1] + b1);
            __half2 v8 = __floats2half2_rn(cacc[j][2] + b0, cacc[j][3] + b1);
            *(__half2*)(g_k + rgg * HH + col)  = v0;
            *(__half2*)(g_k + rgg8 * HH + col) = v8;
        } else {
            float b0 = bv[col], b1 = bv[col + 1];
            size_t bofs = (rgg >> 12) * (size_t)HH * NN;
            size_t n0 = rgg & 4095, n8 = rgg8 & 4095;
            g_vT[bofs + (size_t)col * NN + n0]       = __float2half_rn(cacc[j][0] + b0);
            g_vT[bofs + (size_t)(col + 1) * NN + n0] = __float2half_rn(cacc[j][1] + b1);
            g_vT[bofs + (size_t)col * NN + n8]       = __float2half_rn(cacc[j][2] + b0);
            g_vT[bofs + (size_t)(col + 1) * NN + n8] = __float2half_rn(cacc[j][3] + b1);
        }
    }
#undef LDX
#undef STX
#undef LDW
}

// ---------------------------------------------------------------------------
// Kernel 2: flash attention, pipelined S(kb) -> PV(kb-1) -> exp(kb).
// S uses f16-accumulate mma (accumulator layout == PV A-fragment layout, so
// exp is just ex2h2 on the raw accumulators; no repack). l-mma removed:
// per-thread HADD2 partial sums, quad shuffle-reduced once in the epilogue.
// ---------------------------------------------------------------------------
__global__ void __launch_bounds__(256, 2) attn_kernel(float* __restrict__ out)
{
    extern __shared__ __half smh[];
    __half* s_k = smh;                  // [2][64][LDH]
    __half* s_v = smh + 2 * TILEH;      // [3][64][LDH]  (V^T: rows=d, cols=keys)

    const int tid  = threadIdx.x;
    const int warp = tid >> 5;
    const int lane = tid & 31;
    const int g    = lane >> 2;
    const int tig  = lane & 3;
    const int mat  = lane >> 3;
    const int r8   = lane & 7;
    const int b    = blockIdx.y;
    const int q0   = blockIdx.x * 128;

    const unsigned sk_u = (unsigned)__cvta_generic_to_shared(s_k);
    const unsigned sv_u = (unsigned)__cvta_generic_to_shared(s_v);

    // ---- persistent Q A-fragments (fp16, QSCALE pre-folded) ----
    const __half* qbase = g_q + (size_t)(b * NN + q0 + warp * 16) * HH;
    unsigned qa[4][4];
#pragma unroll
    for (int kk = 0; kk < 4; kk++) {
        qa[kk][0] = *(const unsigned*)(qbase + (size_t)g * HH + 16 * kk + 2 * tig);
        qa[kk][1] = *(const unsigned*)(qbase + (size_t)(g + 8) * HH + 16 * kk + 2 * tig);
        qa[kk][2] = *(const unsigned*)(qbase + (size_t)g * HH + 16 * kk + 2 * tig + 8);
        qa[kk][3] = *(const unsigned*)(qbase + (size_t)(g + 8) * HH + 16 * kk + 2 * tig + 8);
    }

    float oacc[8][4];
#pragma unroll
    for (int j = 0; j < 8; j++)
#pragma unroll
        for (int i = 0; i < 4; i++) oacc[j][i] = 0.0f;
    float lrow0 = 0.0f, lrow8 = 0.0f;   // per-thread partial row sums (2-col slice)
    unsigned paf[4][4];                 // P of previous block, lives across iters

    const __half* gk  = g_k + (size_t)b * NN * HH;
    const __half* gvT = g_vT + (size_t)b * HH * NN;

#define PRE(kb_, kbuf_, vstage_)                                                    \
    do {                                                                            \
        _Pragma("unroll")                                                           \
        for (int u = 0; u < 2; u++) {                                               \
            int id = tid + u * 256;                                                 \
            int row = id >> 3, c16 = id & 7;                                        \
            cp_async16(s_k + (kbuf_) * TILEH + row * LDH + c16 * 8,                 \
                       gk + (size_t)((kb_) * 64 + row) * HH + c16 * 8);             \
            cp_async16(s_v + (vstage_) * TILEH + row * LDH + c16 * 8,               \
                       gvT + (size_t)row * NN + (kb_) * 64 + c16 * 8);              \
        }                                                                           \
        cp_async_commit();                                                          \
    } while (0)

// PV body for block whose P is in paf and whose V tile is at stage vs_
#define PV(vs_)                                                                     \
    do {                                                                            \
        const unsigned va = sv_u + (unsigned)(vs_) * (TILEH * 2) +                  \
                            ((unsigned)(r8 * LDH + mat * 8) << 1);                  \
        _Pragma("unroll")                                                           \
        for (int j = 0; j < 8; j++) {                                               \
            unsigned vf0[4], vf1[4];                                                \
            ldsm4(vf0, va + ((unsigned)(j * 8 * LDH) << 1));                        \
            ldsm4(vf1, va + ((unsigned)(j * 8 * LDH + 32) << 1));                   \
            mmaf16(oacc[j], paf[0], vf0 + 0, oacc[j]);                              \
            mmaf16(oacc[j], paf[1], vf0 + 2, oacc[j]);                              \
            mmaf16(oacc[j], paf[2], vf1 + 0, oacc[j]);                              \
            mmaf16(oacc[j], paf[3], vf1 + 2, oacc[j]);                              \
        }                                                                           \
    } while (0)

    PRE(0, 0, 0);

    int vs_cur = 0;                     // V stage of the current block

    for (int kb = 0; kb < NN / 64; kb++) {
        const int kcur = kb & 1;
        const int vs_nxt  = (vs_cur == 2) ? 0 : vs_cur + 1;
        const int vs_prev = (vs_cur == 0) ? 2 : vs_cur - 1;

        asm volatile("cp.async.wait_group 0;\n");
        __syncthreads();

        if (kb < NN / 64 - 1)
            PRE(kb + 1, kcur ^ 1, vs_nxt);

        // ---- S(kb): f16 accumulate, 8 independent chains ----
        const unsigned ka = sk_u + (unsigned)kcur * (TILEH * 2) +
            ((unsigned)((((mat >> 1) << 3) + r8) * LDH + ((mat & 1) << 3)) << 1);
        unsigned sd[8][2];
#pragma unroll
        for (int c = 0; c < 8; c++) { sd[c][0] = 0u; sd[c][1] = 0u; }

#pragma unroll
        for (int kk = 0; kk < 4; kk++) {
#pragma unroll
            for (int c2 = 0; c2 < 4; c2++) {
                unsigned kf[4];
                ldsm4(kf, ka + ((unsigned)(c2 * 16 * LDH + kk * 16) << 1));
                mmaf16h(sd[2 * c2],     qa[kk], kf + 0, sd[2 * c2]);
                mmaf16h(sd[2 * c2 + 1], qa[kk], kf + 2, sd[2 * c2 + 1]);
            }
        }

        // ---- PV(kb-1): fills the S-chain latency; no deps on S(kb) ----
        if (kb > 0)
            PV(vs_prev);

        // ---- exp(kb): ex2 directly on f16 accumulators (layout == A frag) ----
        // paf[kk] covers keys 16kk..16kk+15: {c=2kk d0(row g), d1(row g+8),
        //                                     c=2kk+1 d0, d1}
#pragma unroll
        for (int cp = 0; cp < 4; cp++) {
            paf[cp][0] = ex2h2(sd[2 * cp][0]);
            paf[cp][1] = ex2h2(sd[2 * cp][1]);
            paf[cp][2] = ex2h2(sd[2 * cp + 1][0]);
            paf[cp][3] = ex2h2(sd[2 * cp + 1][1]);
        }
        // per-thread l partials (row g: even idx; row g+8: odd idx)
        {
            unsigned hg = hadd2u(hadd2u(paf[0][0], paf[0][2]), hadd2u(paf[1][0], paf[1][2]));
            unsigned h8 = hadd2u(hadd2u(paf[0][1], paf[0][3]), hadd2u(paf[1][1], paf[1][3]));
            hg = hadd2u(hg, hadd2u(hadd2u(paf[2][0], paf[2][2]), hadd2u(paf[3][0], paf[3][2])));
            h8 = hadd2u(h8, hadd2u(hadd2u(paf[2][1], paf[2][3]), hadd2u(paf[3][1], paf[3][3])));
            float2 fg = __half22float2(*(__half2*)&hg);
            float2 f8 = __half22float2(*(__half2*)&h8);
            lrow0 += fg.x + fg.y;
            lrow8 += f8.x + f8.y;
        }

        vs_cur = vs_nxt;
    }

    // ---- peeled PV for the last block ----
    {
        const int vs_last = (vs_cur == 0) ? 2 : vs_cur - 1;
        PV(vs_last);
    }

    // ---- l: reduce the 4-lane quad once ----
    lrow0 += __shfl_xor_sync(0xffffffffu, lrow0, 1);
    lrow0 += __shfl_xor_sync(0xffffffffu, lrow0, 2);
    lrow8 += __shfl_xor_sync(0xffffffffu, lrow8, 1);
    lrow8 += __shfl_xor_sync(0xffffffffu, lrow8, 2);
    float inv0 = 1.0f / lrow0;
    float inv8 = 1.0f / lrow8;

    float* orow0 = out + (size_t)(b * NN + q0 + warp * 16 + g) * HH;
    float* orow8 = out + (size_t)(b * NN + q0 + warp * 16 + g + 8) * HH;
#pragma unroll
    for (int j = 0; j < 8; j++) {
        float2 v0 = make_float2(oacc[j][0] * inv0, oacc[j][1] * inv0);
        float2 v8 = make_float2(oacc[j][2] * inv8, oacc[j][3] * inv8);
        *(float2*)(orow0 + j * 8 + 2 * tig) = v0;
        *(float2*)(orow8 + j * 8 + 2 * tig) = v8;
    }
#undef PRE
#undef PV
}

// ---------------------------------------------------------------------------
extern "C" void kernel_launch(void* const* d_in, const int* in_sizes, int n_in,
                              void* d_out, int out_size)
{
    const float* x  = (const float*)d_in[0];
    const float* Wq = (const float*)d_in[1];
    const float* bq = (const float*)d_in[2];
    const float* Wk = (const float*)d_in[3];
    const float* bk = (const float*)d_in[4];
    const float* Wv = (const float*)d_in[5];
    const float* bv = (const float*)d_in[6];
    float* out = (float*)d_out;

    const int smem_proj = (2 * XBUF + 2 * WBUF) * (int)sizeof(__half);   // 73728
    const int smem_attn = 5 * TILEH * (int)sizeof(__half);               // 46080

    (void)cudaFuncSetAttribute(proj_kernel, cudaFuncAttributeMaxDynamicSharedMemorySize, smem_proj);
    (void)cudaFuncSetAttribute(attn_kernel, cudaFuncAttributeMaxDynamicSharedMemorySize, smem_attn);

    wconv_kernel<<<(3 * HH * DD) / 256, 256>>>(Wq, Wk, Wv);
    proj_kernel<<<(BB * NN) / 64, 256, smem_proj>>>(x, bq, bk, bv);
    attn_kernel<<<dim3(NN / 128, BB), 256, smem_attn>>>(out);
}